// round 10
// baseline (speedup 1.0000x reference)
#include <cuda_runtime.h>
#include <math.h>

#define Bsz 8
#define Esz 2000
#define Nsz 10000
#define NRELc 25
#define Ksz 16
#define Tsz 3
#define Lsz 32
#define TAU1f 10.0f
#define BL 256               // B*L columns
#define COL4 64              // BL/4 float4 columns
#define TPB 2                // list entries per block
#define BMW 64               // bitmap words

// ---------------- scratch (static device globals) ----------------
__device__ int      g_heads[Nsz];
__device__ int      g_tails[Nsz];
__device__ int      g_rels[Nsz];
__device__ unsigned g_trips[Nsz];        // head(11b) | rel<<11, CSR by tail
__device__ int      g_rowptr[Esz + 1];
__device__ unsigned g_mask[Esz];         // relation bitmask per tail
__device__ int      g_tidx[Esz];
__device__ int      g_ent[Bsz];
__device__ float    g_val[Bsz];
__device__ float    g_wp[Tsz * NRELc * Lsz];        // [t][r][l]
__device__ float    g_shp[Tsz * (NRELc - 1) * Lsz]; // [t][j][l]
__device__ float    g_shtp[Tsz * Ksz * Lsz];        // [t][k][l]
__device__ float    g_ab[Tsz * Lsz * 2];
__device__ float    g_tw[Lsz];
__device__ unsigned g_bm0[BMW];          // nonzero rows of s0
__device__ unsigned g_bm1[BMW];          // nonzero rows of s1
__device__ int      g_list1[Esz], g_list2[Esz];
__device__ int      g_cnt1, g_cnt2;
__device__ float    g_sA[Esz * BL];      // s0, [e][b*32+l]
__device__ float    g_sB[Esz * BL];      // s1

__device__ __forceinline__ float clip01(float x) { return fminf(fmaxf(x, 0.0f), 1.0f); }

// ============ 1) streaming extraction + zero the output ============
__global__ void k_setup(const float4* __restrict__ e2t,
                        const float4* __restrict__ t2e,
                        const float4* __restrict__ t2r,
                        const float*  __restrict__ input_x,
                        const float*  __restrict__ type_mat,
                        float* __restrict__ out) {
    unsigned tid = blockIdx.x * blockDim.x + threadIdx.x;
    unsigned stride = gridDim.x * blockDim.x;

    for (unsigned i = tid; i < Bsz * Esz; i += stride) {
        out[i] = 0.0f;                    // zero the poisoned output
        float v = input_x[i];
        if (v != 0.0f) { g_ent[i / Esz] = (int)(i % Esz); g_val[i / Esz] = v; }
    }
    for (unsigned i = tid; i < Esz * Ksz; i += stride)
        if (type_mat[i] != 0.0f) g_tidx[i / Ksz] = (int)(i % Ksz);

    const unsigned n3 = Nsz * NRELc / 4;
    for (unsigned i = tid; i < n3; i += stride) {
        float4 v = t2r[i];
        unsigned base = i * 4u;
        if (v.x != 0.0f) { unsigned id = base + 0; g_rels[id / NRELc] = (int)(id % NRELc); }
        if (v.y != 0.0f) { unsigned id = base + 1; g_rels[id / NRELc] = (int)(id % NRELc); }
        if (v.z != 0.0f) { unsigned id = base + 2; g_rels[id / NRELc] = (int)(id % NRELc); }
        if (v.w != 0.0f) { unsigned id = base + 3; g_rels[id / NRELc] = (int)(id % NRELc); }
    }
    const unsigned n1 = (unsigned)Esz * Nsz / 4;   // e2triple [E,N] -> heads
    for (unsigned i = tid; i < n1; i += stride) {
        float4 v = e2t[i];
        unsigned base = i * 4u;
        if (v.x != 0.0f) { unsigned id = base + 0; g_heads[id % Nsz] = (int)(id / Nsz); }
        if (v.y != 0.0f) { unsigned id = base + 1; g_heads[id % Nsz] = (int)(id / Nsz); }
        if (v.z != 0.0f) { unsigned id = base + 2; g_heads[id % Nsz] = (int)(id / Nsz); }
        if (v.w != 0.0f) { unsigned id = base + 3; g_heads[id % Nsz] = (int)(id / Nsz); }
    }
    const unsigned n2 = (unsigned)Nsz * Esz / 4;   // triple2e [N,E] -> tails
    for (unsigned i = tid; i < n2; i += stride) {
        float4 v = t2e[i];
        unsigned base = i * 4u;
        if (v.x != 0.0f) { unsigned id = base + 0; g_tails[id / Esz] = (int)(id % Esz); }
        if (v.y != 0.0f) { unsigned id = base + 1; g_tails[id / Esz] = (int)(id % Esz); }
        if (v.z != 0.0f) { unsigned id = base + 2; g_tails[id / Esz] = (int)(id % Esz); }
        if (v.w != 0.0f) { unsigned id = base + 3; g_tails[id / Esz] = (int)(id % Esz); }
    }
}

// ============ 2) single block: join, bitmaps/lists, scan, fill, tables, hx0, inline s0 ============
__global__ void __launch_bounds__(1024, 1)
k_mid(const float* __restrict__ alpha, const float* __restrict__ beta,
      const float* __restrict__ alpha_x, const float* __restrict__ beta_x,
      const float* __restrict__ h_x, const float* __restrict__ h_x_type,
      const float* __restrict__ type_mat, const float* __restrict__ w,
      const float* __restrict__ h, const float* __restrict__ h_type,
      const float* __restrict__ weight) {
    __shared__ int      scnt[Esz];
    __shared__ unsigned smask[Esz];
    __shared__ int      sfill[Esz];
    __shared__ int      sscan[1024];
    __shared__ int      slist0[Esz];
    __shared__ float    shx[Bsz * NRELc];
    __shared__ float    shxb[Bsz * (NRELc - 1)];
    __shared__ float    s_hx0[BL];
    __shared__ int      sent[Bsz];
    __shared__ float    sval[Bsz];
    __shared__ unsigned sbm0[BMW], sbm1[BMW], sbm2[BMW];
    __shared__ int      scl[3];

    int t = threadIdx.x;
    for (int i = t; i < Esz; i += 1024) { scnt[i] = 0; smask[i] = 0u; }
    if (t < Bsz * NRELc) shx[t] = 0.0f;
    if (t < Bsz) { sent[t] = g_ent[t]; sval[t] = g_val[t]; }
    if (t < BMW) { sbm0[t] = 0u; sbm1[t] = 0u; sbm2[t] = 0u; }
    if (t == 0) { scl[0] = 0; scl[1] = 0; scl[2] = 0; }
    __syncthreads();

    // join pass: counts, masks, hx, bm0
    for (int n = t; n < Nsz; n += 1024) {
        int tl = g_tails[n], r = g_rels[n], hd = g_heads[n];
        atomicAdd(&scnt[tl], 1);
        if (r < NRELc - 1) atomicOr(&smask[tl], 1u << r);
        bool hit = false;
#pragma unroll
        for (int b = 0; b < Bsz; b++)
            if (hd == sent[b]) { atomicAdd(&shx[b * NRELc + r], sval[b]); hit = true; }
        if (hit) atomicOr(&sbm0[tl >> 5], 1u << (tl & 31));
    }
    __syncthreads();
    // bm1
    for (int n = t; n < Nsz; n += 1024) {
        int tl = g_tails[n], hd = g_heads[n];
        if ((sbm0[hd >> 5] >> (hd & 31)) & 1u)
            atomicOr(&sbm1[tl >> 5], 1u << (tl & 31));
    }
    __syncthreads();
    // bm2
    for (int n = t; n < Nsz; n += 1024) {
        int tl = g_tails[n], hd = g_heads[n];
        if ((sbm1[hd >> 5] >> (hd & 31)) & 1u)
            atomicOr(&sbm2[tl >> 5], 1u << (tl & 31));
    }
    __syncthreads();

    if (t < BMW) { g_bm0[t] = sbm0[t]; g_bm1[t] = sbm1[t]; }
    for (int i = t; i < Esz; i += 1024) {
        g_mask[i] = smask[i];
        if ((sbm0[i >> 5] >> (i & 31)) & 1u) { int p = atomicAdd(&scl[0], 1); slist0[p] = i; }
        if ((sbm1[i >> 5] >> (i & 31)) & 1u) { int p = atomicAdd(&scl[1], 1); g_list1[p] = i; }
        if ((sbm2[i >> 5] >> (i & 31)) & 1u) { int p = atomicAdd(&scl[2], 1); g_list2[p] = i; }
    }

    // tables
    if (t < Tsz * Lsz) {
        int tt = t / Lsz, l = t % Lsz;
        const float* wr = w + (tt * Lsz + l) * NRELc;
        float m = -1e30f;
#pragma unroll
        for (int r = 0; r < NRELc; r++) m = fmaxf(m, wr[r]);
        float s = 0.0f, ev[NRELc];
#pragma unroll
        for (int r = 0; r < NRELc; r++) { ev[r] = expf(wr[r] - m); s += ev[r]; }
        float inv = 1.0f / s;
#pragma unroll
        for (int r = 0; r < NRELc; r++)
            g_wp[(tt * NRELc + r) * Lsz + l] = ev[r] * inv;
        g_ab[(tt * Lsz + l) * 2 + 0] = clip01(alpha[tt * Lsz + l] / TAU1f);
        g_ab[(tt * Lsz + l) * 2 + 1] = clip01(beta[tt * Lsz + l] / TAU1f);
    }
    for (int i = t; i < Tsz * (NRELc - 1) * Lsz; i += 1024) {
        int tt = i / ((NRELc - 1) * Lsz);
        int rem = i % ((NRELc - 1) * Lsz);
        int j = rem / Lsz, l = rem % Lsz;
        g_shp[i] = clip01(h[(tt * Lsz + l) * (NRELc - 1) + j] / TAU1f);
    }
    for (int i = t; i < Tsz * Ksz * Lsz; i += 1024) {
        int tt = i / (Ksz * Lsz);
        int rem = i % (Ksz * Lsz);
        int k = rem / Lsz, l = rem % Lsz;
        g_shtp[i] = clip01(h_type[(tt * Lsz + l) * Ksz + k] / TAU1f);
    }
    if (t < Lsz) g_tw[t] = tanhf(weight[t]);

    // exclusive scan of tail counts -> rowptr
    int c0 = (2 * t < Esz) ? scnt[2 * t] : 0;
    int c1 = (2 * t + 1 < Esz) ? scnt[2 * t + 1] : 0;
    sscan[t] = c0 + c1;
    __syncthreads();
    for (int off = 1; off < 1024; off <<= 1) {
        int v = (t >= off) ? sscan[t - off] : 0;
        __syncthreads();
        sscan[t] += v;
        __syncthreads();
    }
    int excl = (t > 0) ? sscan[t - 1] : 0;
    if (2 * t < Esz)     { g_rowptr[2 * t] = excl;          sfill[2 * t] = excl; }
    if (2 * t + 1 < Esz) { g_rowptr[2 * t + 1] = excl + c0; sfill[2 * t + 1] = excl + c0; }
    if (t == 0) { g_rowptr[Esz] = Nsz; g_cnt1 = scl[1]; g_cnt2 = scl[2]; }

    if (t < Bsz * (NRELc - 1)) {
        int b = t / (NRELc - 1), j = t % (NRELc - 1);
        int col = (j < 12) ? (12 + j) : (j - 12);
        shxb[t] = clip01(shx[b * NRELc + col]);
    }
    __syncthreads();

    // hx0 -> smem
    if (t < BL) {
        int b = t / Lsz, l = t % Lsz;
        float a  = clip01(alpha[l] / TAU1f);
        float bb = clip01(beta[l] / TAU1f);
        float gate = 1.0f - clip01(clip01(alpha_x[l] / TAU1f) + clip01(beta_x[l] / TAU1f));
        float htx = 0.0f;
#pragma unroll
        for (int k = 0; k < Ksz; k++)
            htx += type_mat[sent[b] * Ksz + k] * clip01(h_x_type[l * Ksz + k] / TAU1f);
        htx *= sval[b];
        float hxl = 0.0f;
#pragma unroll
        for (int j = 0; j < NRELc - 1; j++)
            hxl += shxb[b * (NRELc - 1) + j] * clip01(h_x[l * (NRELc - 1) + j] / TAU1f);
        s_hx0[t] = clip01(a * htx + bb * hxl) + gate;
    }
    __syncthreads();

    // fill tail-CSR
    for (int n = t; n < Nsz; n += 1024) {
        int tl = g_tails[n];
        int pos = atomicAdd(&sfill[tl], 1);
        g_trips[pos] = (unsigned)g_heads[n] | ((unsigned)g_rels[n] << 11);
    }
    __syncthreads();

    // ---- inline s0 computation over list0 (16 groups x 64 threads) ----
    {
        int grp = t >> 6, c = t & 63, b = c >> 3;
        int cnt0 = scl[0];
        for (int i = grp; i < cnt0; i += 16) {
            int e = slist0[i];
            int rb = g_rowptr[e], re = g_rowptr[e + 1];
            float4 acc = make_float4(0.f, 0.f, 0.f, 0.f);
            for (int j = rb; j < re; j++) {
                unsigned u = g_trips[j];
                int head = (int)(u & 0x7ffu);
                unsigned rel = u >> 11;
                if (head == sent[b]) {
                    float4 wv = ((const float4*)g_wp)[(0 * NRELc + rel) * 8 + (c & 7)];
                    acc.x = fmaf(sval[b], wv.x, acc.x);
                    acc.y = fmaf(sval[b], wv.y, acc.y);
                    acc.z = fmaf(sval[b], wv.z, acc.z);
                    acc.w = fmaf(sval[b], wv.w, acc.w);
                }
            }
            // hid[l,e] for the 4 l's of this slot
            int l0 = (c & 7) * 4;
            float4 val;
            float* vp = (float*)&val;
            float* ap = (float*)&acc;
#pragma unroll
            for (int q = 0; q < 4; q++) {
                int l = l0 + q;
                float a  = g_ab[(0 * Lsz + l) * 2 + 0];
                float bb = g_ab[(0 * Lsz + l) * 2 + 1];
                float s1 = g_shtp[(0 * Ksz + g_tidx[e]) * Lsz + l];
                float s2 = 0.0f;
                unsigned m = smask[e];
                while (m) { int jj = __ffs(m) - 1; s2 += g_shp[(0 * (NRELc - 1) + jj) * Lsz + l]; m &= m - 1; }
                float hid = clip01(a * s1 + bb * s2) + (1.0f - clip01(a + bb));
                vp[q] = ap[q] * hid * s_hx0[b * Lsz + l];
            }
            ((float4*)g_sA)[e * COL4 + c] = val;
        }
    }
}

// ============ 3) propagation over active lists ============
template <int T>
__global__ void __launch_bounds__(TPB * COL4)
k_prop(float* __restrict__ out) {
    const int cnt = (T == 1) ? g_cnt1 : g_cnt2;
    if (blockIdx.x * TPB >= cnt) return;

    const int tid = threadIdx.x;
    const int g = tid >> 6;
    const int c = tid & 63;
    const int b = c >> 3;
    const int* lst = (T == 1) ? g_list1 : g_list2;
    const int idx = min(blockIdx.x * TPB + g, cnt - 1);
    const int e = lst[idx];

    __shared__ float shid[TPB][Lsz];
    __shared__ unsigned sbm[BMW];
    __shared__ int se[TPB];

    if (tid < BMW) sbm[tid] = (T == 1) ? g_bm0[tid] : g_bm1[tid];
    if (tid < TPB) se[tid] = lst[min(blockIdx.x * TPB + tid, cnt - 1)];

    if (tid >= 64 && tid < 64 + TPB * Lsz) {
        int k = tid - 64;
        int gg = k >> 5, l = k & 31;
        __syncwarp();  // se visibility handled by syncthreads below; compute after
    }
    __syncthreads();

    if (tid < TPB * Lsz) {
        int gg = tid >> 5, l = tid & 31;
        int ee = se[gg];
        float a  = g_ab[(T * Lsz + l) * 2 + 0];
        float bb = g_ab[(T * Lsz + l) * 2 + 1];
        float s1 = g_shtp[(T * Ksz + g_tidx[ee]) * Lsz + l];
        float s2 = 0.0f;
        unsigned m = g_mask[ee];
        while (m) { int jj = __ffs(m) - 1; s2 += g_shp[(T * (NRELc - 1) + jj) * Lsz + l]; m &= m - 1; }
        shid[gg][l] = clip01(a * s1 + bb * s2) + (1.0f - clip01(a + bb));
    }
    __syncthreads();

    const float4* prevbuf = (const float4*)((T == 1) ? g_sA : g_sB);
    float4* dstbuf = (float4*)g_sB;
    const float4* wp4 = (const float4*)g_wp;

    const int beg = g_rowptr[e];
    const int end = g_rowptr[e + 1];

    float4 acc = make_float4(0.f, 0.f, 0.f, 0.f);
    int j = beg;
    unsigned u_next = (j < end) ? __ldg(&g_trips[j]) : 0u;
    while (j < end) {
        unsigned u = u_next;
        if (j + 1 < end) u_next = __ldg(&g_trips[j + 1]);
        unsigned head = u & 0x7ffu;
        unsigned rel  = u >> 11;
        if ((sbm[head >> 5] >> (head & 31)) & 1u) {
            float4 v = prevbuf[head * COL4 + c];
            float4 wv = wp4[(T * NRELc + rel) * 8 + (c & 7)];
            acc.x = fmaf(v.x, wv.x, acc.x);
            acc.y = fmaf(v.y, wv.y, acc.y);
            acc.z = fmaf(v.z, wv.z, acc.z);
            acc.w = fmaf(v.w, wv.w, acc.w);
        }
        ++j;
    }

    float4 hid = ((const float4*)shid[g])[c & 7];
    float4 val = make_float4(acc.x * hid.x, acc.y * hid.y, acc.z * hid.z, acc.w * hid.w);

    if (T == 2) {
        float4 tw = ((const float4*)g_tw)[c & 7];
        float r = val.x * tw.x + val.y * tw.y + val.z * tw.z + val.w * tw.w;
#pragma unroll
        for (int off = 4; off > 0; off >>= 1)
            r += __shfl_xor_sync(0xffffffffu, r, off);
        if ((c & 7) == 0) out[b * Esz + e] = r;
    } else {
        dstbuf[e * COL4 + c] = val;
    }
}

// ---------------- launch ----------------
extern "C" void kernel_launch(void* const* d_in, const int* in_sizes, int n_in,
                              void* d_out, int out_size) {
    const float* input_x  = (const float*)d_in[0];
    const float* type_mat = (const float*)d_in[1];
    const float* e2triple = (const float*)d_in[2];
    const float* triple2e = (const float*)d_in[3];
    const float* triple2r = (const float*)d_in[4];
    const float* w        = (const float*)d_in[5];
    const float* weight   = (const float*)d_in[6];
    const float* h        = (const float*)d_in[7];
    const float* h_x      = (const float*)d_in[8];
    const float* h_type   = (const float*)d_in[9];
    const float* h_x_type = (const float*)d_in[10];
    const float* alpha    = (const float*)d_in[11];
    const float* beta     = (const float*)d_in[12];
    const float* alpha_x  = (const float*)d_in[13];
    const float* beta_x   = (const float*)d_in[14];
    float* out = (float*)d_out;

    k_setup<<<1184, 256>>>((const float4*)e2triple, (const float4*)triple2e,
                           (const float4*)triple2r, input_x, type_mat, out);
    k_mid<<<1, 1024>>>(alpha, beta, alpha_x, beta_x, h_x, h_x_type,
                       type_mat, w, h, h_type, weight);
    k_prop<1><<<Esz / TPB, TPB * COL4>>>(out);
    k_prop<2><<<Esz / TPB, TPB * COL4>>>(out);
}

// round 11
// speedup vs baseline: 1.0535x; 1.0535x over previous
#include <cuda_runtime.h>
#include <math.h>

#define Bsz 8
#define Esz 2000
#define Nsz 10000
#define NRELc 25
#define Ksz 16
#define Tsz 3
#define Lsz 32
#define TAU1f 10.0f
#define BL 256               // B*L columns
#define COL4 64              // BL/4 float4 columns
#define TPB 2                // tails (or list entries) per block
#define BMW 64               // bitmap words

// ---------------- scratch (static device globals) ----------------
__device__ int      g_heads[Nsz];
__device__ int      g_tails[Nsz];
__device__ int      g_rels[Nsz];
__device__ unsigned g_trips[Nsz];        // head(11b) | rel<<11, CSR by tail
__device__ int      g_rowptr[Esz + 1];
__device__ unsigned g_mask[Esz];         // relation bitmask per tail
__device__ int      g_tidx[Esz];
__device__ int      g_ent[Bsz];
__device__ float    g_val[Bsz];
__device__ float    g_hx0[BL];
__device__ float    g_wp[Tsz * NRELc * Lsz];        // [t][r][l]
__device__ float    g_shp[Tsz * (NRELc - 1) * Lsz]; // [t][j][l]
__device__ float    g_shtp[Tsz * Ksz * Lsz];        // [t][k][l]
__device__ float    g_ab[Tsz * Lsz * 2];
__device__ float    g_tw[Lsz];
__device__ unsigned g_bm0[BMW];          // nonzero rows of s0
__device__ unsigned g_bm1[BMW];          // nonzero rows of s1
__device__ int      g_list0[Esz], g_list1[Esz];
__device__ int      g_cnt0, g_cnt1;
__device__ float    g_sA[Esz * BL];      // s0, [e][b*32+l]
__device__ float    g_sB[Esz * BL];      // s1

__device__ __forceinline__ float clip01(float x) { return fminf(fmaxf(x, 0.0f), 1.0f); }

// ============ 1) streaming extraction ============
__global__ void k_setup(const float4* __restrict__ e2t,
                        const float4* __restrict__ t2e,
                        const float4* __restrict__ t2r,
                        const float*  __restrict__ input_x,
                        const float*  __restrict__ type_mat) {
    unsigned tid = blockIdx.x * blockDim.x + threadIdx.x;
    unsigned stride = gridDim.x * blockDim.x;

    for (unsigned i = tid; i < Bsz * Esz; i += stride) {
        float v = input_x[i];
        if (v != 0.0f) { g_ent[i / Esz] = (int)(i % Esz); g_val[i / Esz] = v; }
    }
    for (unsigned i = tid; i < Esz * Ksz; i += stride)
        if (type_mat[i] != 0.0f) g_tidx[i / Ksz] = (int)(i % Ksz);

    const unsigned n3 = Nsz * NRELc / 4;
    for (unsigned i = tid; i < n3; i += stride) {
        float4 v = t2r[i];
        unsigned base = i * 4u;
        if (v.x != 0.0f) { unsigned id = base + 0; g_rels[id / NRELc] = (int)(id % NRELc); }
        if (v.y != 0.0f) { unsigned id = base + 1; g_rels[id / NRELc] = (int)(id % NRELc); }
        if (v.z != 0.0f) { unsigned id = base + 2; g_rels[id / NRELc] = (int)(id % NRELc); }
        if (v.w != 0.0f) { unsigned id = base + 3; g_rels[id / NRELc] = (int)(id % NRELc); }
    }
    const unsigned n1 = (unsigned)Esz * Nsz / 4;   // e2triple [E,N] -> heads
    for (unsigned i = tid; i < n1; i += stride) {
        float4 v = e2t[i];
        unsigned base = i * 4u;
        if (v.x != 0.0f) { unsigned id = base + 0; g_heads[id % Nsz] = (int)(id / Nsz); }
        if (v.y != 0.0f) { unsigned id = base + 1; g_heads[id % Nsz] = (int)(id / Nsz); }
        if (v.z != 0.0f) { unsigned id = base + 2; g_heads[id % Nsz] = (int)(id / Nsz); }
        if (v.w != 0.0f) { unsigned id = base + 3; g_heads[id % Nsz] = (int)(id / Nsz); }
    }
    const unsigned n2 = (unsigned)Nsz * Esz / 4;   // triple2e [N,E] -> tails
    for (unsigned i = tid; i < n2; i += stride) {
        float4 v = t2e[i];
        unsigned base = i * 4u;
        if (v.x != 0.0f) { unsigned id = base + 0; g_tails[id / Esz] = (int)(id % Esz); }
        if (v.y != 0.0f) { unsigned id = base + 1; g_tails[id / Esz] = (int)(id % Esz); }
        if (v.z != 0.0f) { unsigned id = base + 2; g_tails[id / Esz] = (int)(id % Esz); }
        if (v.w != 0.0f) { unsigned id = base + 3; g_tails[id / Esz] = (int)(id % Esz); }
    }
}

// ============ 2) single block: join, bitmaps+lists, scan, fill, tables, hx0 ============
__global__ void __launch_bounds__(1024, 1)
k_mid(const float* __restrict__ alpha, const float* __restrict__ beta,
      const float* __restrict__ alpha_x, const float* __restrict__ beta_x,
      const float* __restrict__ h_x, const float* __restrict__ h_x_type,
      const float* __restrict__ type_mat, const float* __restrict__ w,
      const float* __restrict__ h, const float* __restrict__ h_type,
      const float* __restrict__ weight) {
    __shared__ int      scnt[Esz];
    __shared__ unsigned smask[Esz];
    __shared__ int      sfill[Esz];
    __shared__ int      sscan[1024];
    __shared__ float    shx[Bsz * NRELc];
    __shared__ float    shxb[Bsz * (NRELc - 1)];
    __shared__ int      sent[Bsz];
    __shared__ float    sval[Bsz];
    __shared__ unsigned sbm0[BMW], sbm1[BMW];
    __shared__ int      scl[2];

    int t = threadIdx.x;
    for (int i = t; i < Esz; i += 1024) { scnt[i] = 0; smask[i] = 0u; }
    if (t < Bsz * NRELc) shx[t] = 0.0f;
    if (t < Bsz) { sent[t] = g_ent[t]; sval[t] = g_val[t]; }
    if (t < BMW) { sbm0[t] = 0u; sbm1[t] = 0u; }
    if (t == 0) { scl[0] = 0; scl[1] = 0; }
    __syncthreads();

    // join pass: counts, masks, hx accumulation, bm0
    for (int n = t; n < Nsz; n += 1024) {
        int tl = g_tails[n], r = g_rels[n], hd = g_heads[n];
        atomicAdd(&scnt[tl], 1);
        if (r < NRELc - 1) atomicOr(&smask[tl], 1u << r);
        bool hit = false;
#pragma unroll
        for (int b = 0; b < Bsz; b++)
            if (hd == sent[b]) { atomicAdd(&shx[b * NRELc + r], sval[b]); hit = true; }
        if (hit) atomicOr(&sbm0[tl >> 5], 1u << (tl & 31));
    }
    __syncthreads();
    // bm1: tails reachable from bm0 rows
    for (int n = t; n < Nsz; n += 1024) {
        int tl = g_tails[n], hd = g_heads[n];
        if ((sbm0[hd >> 5] >> (hd & 31)) & 1u)
            atomicOr(&sbm1[tl >> 5], 1u << (tl & 31));
    }
    __syncthreads();

    if (t < BMW) { g_bm0[t] = sbm0[t]; g_bm1[t] = sbm1[t]; }
    for (int i = t; i < Esz; i += 1024) {
        g_mask[i] = smask[i];
        if ((sbm0[i >> 5] >> (i & 31)) & 1u) { int p = atomicAdd(&scl[0], 1); g_list0[p] = i; }
        if ((sbm1[i >> 5] >> (i & 31)) & 1u) { int p = atomicAdd(&scl[1], 1); g_list1[p] = i; }
    }

    // ---- precompute tables ----
    if (t < Tsz * Lsz) {
        int tt = t / Lsz, l = t % Lsz;
        const float* wr = w + (tt * Lsz + l) * NRELc;
        float m = -1e30f;
#pragma unroll
        for (int r = 0; r < NRELc; r++) m = fmaxf(m, wr[r]);
        float s = 0.0f, ev[NRELc];
#pragma unroll
        for (int r = 0; r < NRELc; r++) { ev[r] = expf(wr[r] - m); s += ev[r]; }
        float inv = 1.0f / s;
#pragma unroll
        for (int r = 0; r < NRELc; r++)
            g_wp[(tt * NRELc + r) * Lsz + l] = ev[r] * inv;
        g_ab[(tt * Lsz + l) * 2 + 0] = clip01(alpha[tt * Lsz + l] / TAU1f);
        g_ab[(tt * Lsz + l) * 2 + 1] = clip01(beta[tt * Lsz + l] / TAU1f);
    }
    for (int i = t; i < Tsz * (NRELc - 1) * Lsz; i += 1024) {
        int tt = i / ((NRELc - 1) * Lsz);
        int rem = i % ((NRELc - 1) * Lsz);
        int j = rem / Lsz, l = rem % Lsz;
        g_shp[i] = clip01(h[(tt * Lsz + l) * (NRELc - 1) + j] / TAU1f);
    }
    for (int i = t; i < Tsz * Ksz * Lsz; i += 1024) {
        int tt = i / (Ksz * Lsz);
        int rem = i % (Ksz * Lsz);
        int k = rem / Lsz, l = rem % Lsz;
        g_shtp[i] = clip01(h_type[(tt * Lsz + l) * Ksz + k] / TAU1f);
    }
    if (t < Lsz) g_tw[t] = tanhf(weight[t]);

    // ---- exclusive scan ----
    int c0 = (2 * t < Esz) ? scnt[2 * t] : 0;
    int c1 = (2 * t + 1 < Esz) ? scnt[2 * t + 1] : 0;
    sscan[t] = c0 + c1;
    __syncthreads();
    for (int off = 1; off < 1024; off <<= 1) {
        int v = (t >= off) ? sscan[t - off] : 0;
        __syncthreads();
        sscan[t] += v;
        __syncthreads();
    }
    int excl = (t > 0) ? sscan[t - 1] : 0;
    if (2 * t < Esz)     { g_rowptr[2 * t] = excl;          sfill[2 * t] = excl; }
    if (2 * t + 1 < Esz) { g_rowptr[2 * t + 1] = excl + c0; sfill[2 * t + 1] = excl + c0; }
    if (t == 0) { g_rowptr[Esz] = Nsz; g_cnt0 = scl[0]; g_cnt1 = scl[1]; }

    if (t < Bsz * (NRELc - 1)) {
        int b = t / (NRELc - 1), j = t % (NRELc - 1);
        int col = (j < 12) ? (12 + j) : (j - 12);
        shxb[t] = clip01(shx[b * NRELc + col]);
    }
    __syncthreads();

    if (t < BL) {
        int b = t / Lsz, l = t % Lsz;
        float a  = clip01(alpha[l] / TAU1f);
        float bb = clip01(beta[l] / TAU1f);
        float gate = 1.0f - clip01(clip01(alpha_x[l] / TAU1f) + clip01(beta_x[l] / TAU1f));
        float htx = 0.0f;
#pragma unroll
        for (int k = 0; k < Ksz; k++)
            htx += type_mat[sent[b] * Ksz + k] * clip01(h_x_type[l * Ksz + k] / TAU1f);
        htx *= sval[b];
        float hxl = 0.0f;
#pragma unroll
        for (int j = 0; j < NRELc - 1; j++)
            hxl += shxb[b * (NRELc - 1) + j] * clip01(h_x[l * (NRELc - 1) + j] / TAU1f);
        g_hx0[t] = clip01(a * htx + bb * hxl) + gate;
    }
    __syncthreads();

    // counting-sort fill: head | rel<<11
    for (int n = t; n < Nsz; n += 1024) {
        int tl = g_tails[n];
        int pos = atomicAdd(&sfill[tl], 1);
        g_trips[pos] = (unsigned)g_heads[n] | ((unsigned)g_rels[n] << 11);
    }
}

// ============ 3) propagation ============
// T=0: over list0, no loads (entity predicate), writes g_sA rows in bm0.
// T=1: over list1, bm0-filtered loads of g_sA, writes g_sB rows in bm1.
// T=2: dense over all tails, bm1-filtered loads of g_sB, reduces into out.
template <int T>
__global__ void __launch_bounds__(TPB * COL4)
k_prop(float* __restrict__ out) {
    int cnt;
    if (T == 0)      cnt = g_cnt0;
    else if (T == 1) cnt = g_cnt1;
    else             cnt = Esz;
    if (blockIdx.x * TPB >= cnt) return;

    const int tid = threadIdx.x;
    const int g = tid >> 6;          // local slot 0..1
    const int c = tid & 63;          // float4 column slot
    const int b = c >> 3;

    __shared__ float shid[TPB][Lsz];
    __shared__ unsigned sbm[BMW];
    __shared__ int se[TPB];

    const int idx = blockIdx.x * TPB + g;
    const bool active = (idx < cnt);

    if (T == 1 && tid < BMW) sbm[tid] = g_bm0[tid];
    if (T == 2 && tid < BMW) sbm[tid] = g_bm1[tid];
    if (tid < TPB) {
        int ii = blockIdx.x * TPB + tid;
        if (T == 2) se[tid] = min(ii, Esz - 1);
        else        se[tid] = (T == 0 ? g_list0 : g_list1)[min(ii, cnt - 1)];
    }
    __syncthreads();

    if (tid < TPB * Lsz) {
        int gg = tid >> 5, l = tid & 31;
        int ee = se[gg];
        float a  = g_ab[(T * Lsz + l) * 2 + 0];
        float bb = g_ab[(T * Lsz + l) * 2 + 1];
        float s1 = g_shtp[(T * Ksz + g_tidx[ee]) * Lsz + l];
        float s2 = 0.0f;
        unsigned m = g_mask[ee];
        while (m) { int jj = __ffs(m) - 1; s2 += g_shp[(T * (NRELc - 1) + jj) * Lsz + l]; m &= m - 1; }
        shid[gg][l] = clip01(a * s1 + bb * s2) + (1.0f - clip01(a + bb));
    }
    __syncthreads();

    const int e = se[g];
    const float4* prevbuf = (const float4*)((T == 1) ? g_sA : g_sB);
    float4* dstbuf = (float4*)((T == 0) ? g_sA : g_sB);
    const float4* wp4 = (const float4*)g_wp;

    int sentb = 0; float svalb = 0.0f;
    if (T == 0) { sentb = g_ent[b]; svalb = g_val[b]; }

    const int beg = g_rowptr[e];
    const int end = g_rowptr[e + 1];

    float4 acc = make_float4(0.f, 0.f, 0.f, 0.f);
    int j = beg;
    unsigned u_next = (j < end) ? __ldg(&g_trips[j]) : 0u;
    while (j < end) {
        unsigned u = u_next;
        if (j + 1 < end) u_next = __ldg(&g_trips[j + 1]);
        unsigned head = u & 0x7ffu;
        unsigned rel  = u >> 11;
        if (T == 0) {
            if ((int)head == sentb) {
                float4 wv = wp4[(T * NRELc + rel) * 8 + (c & 7)];
                acc.x = fmaf(svalb, wv.x, acc.x);
                acc.y = fmaf(svalb, wv.y, acc.y);
                acc.z = fmaf(svalb, wv.z, acc.z);
                acc.w = fmaf(svalb, wv.w, acc.w);
            }
        } else {
            if ((sbm[head >> 5] >> (head & 31)) & 1u) {
                float4 v = prevbuf[head * COL4 + c];
                float4 wv = wp4[(T * NRELc + rel) * 8 + (c & 7)];
                acc.x = fmaf(v.x, wv.x, acc.x);
                acc.y = fmaf(v.y, wv.y, acc.y);
                acc.z = fmaf(v.z, wv.z, acc.z);
                acc.w = fmaf(v.w, wv.w, acc.w);
            }
        }
        ++j;
    }

    float4 hid = ((const float4*)shid[g])[c & 7];
    float4 val;
    if (T == 0) {
        float4 sc = ((const float4*)g_hx0)[c];
        val = make_float4(acc.x * hid.x * sc.x, acc.y * hid.y * sc.y,
                          acc.z * hid.z * sc.z, acc.w * hid.w * sc.w);
    } else {
        val = make_float4(acc.x * hid.x, acc.y * hid.y, acc.z * hid.z, acc.w * hid.w);
    }

    if (T == 2) {
        float4 tw = ((const float4*)g_tw)[c & 7];
        float r = val.x * tw.x + val.y * tw.y + val.z * tw.z + val.w * tw.w;
#pragma unroll
        for (int off = 4; off > 0; off >>= 1)
            r += __shfl_xor_sync(0xffffffffu, r, off);
        if ((c & 7) == 0) out[b * Esz + e] = r;
    } else if (active) {
        dstbuf[e * COL4 + c] = val;
    }
}

// ---------------- launch ----------------
extern "C" void kernel_launch(void* const* d_in, const int* in_sizes, int n_in,
                              void* d_out, int out_size) {
    const float* input_x  = (const float*)d_in[0];
    const float* type_mat = (const float*)d_in[1];
    const float* e2triple = (const float*)d_in[2];
    const float* triple2e = (const float*)d_in[3];
    const float* triple2r = (const float*)d_in[4];
    const float* w        = (const float*)d_in[5];
    const float* weight   = (const float*)d_in[6];
    const float* h        = (const float*)d_in[7];
    const float* h_x      = (const float*)d_in[8];
    const float* h_type   = (const float*)d_in[9];
    const float* h_x_type = (const float*)d_in[10];
    const float* alpha    = (const float*)d_in[11];
    const float* beta     = (const float*)d_in[12];
    const float* alpha_x  = (const float*)d_in[13];
    const float* beta_x   = (const float*)d_in[14];
    float* out = (float*)d_out;

    k_setup<<<1184, 256>>>((const float4*)e2triple, (const float4*)triple2e,
                           (const float4*)triple2r, input_x, type_mat);
    k_mid<<<1, 1024>>>(alpha, beta, alpha_x, beta_x, h_x, h_x_type,
                       type_mat, w, h, h_type, weight);
    k_prop<0><<<Esz / TPB, TPB * COL4>>>(out);
    k_prop<1><<<Esz / TPB, TPB * COL4>>>(out);
    k_prop<2><<<Esz / TPB, TPB * COL4>>>(out);
}

// round 12
// speedup vs baseline: 1.0570x; 1.0034x over previous
#include <cuda_runtime.h>
#include <math.h>

#define Bsz 8
#define Esz 2000
#define Nsz 10000
#define NRELc 25
#define Ksz 16
#define Tsz 3
#define Lsz 32
#define TAU1f 10.0f
#define BL 256               // B*L columns
#define COL4 64              // BL/4 float4 columns
#define TPB 2                // tails per block
#define BMW 64               // bitmap words
#define PGRID (Esz / TPB)    // 1000 blocks

// ---------------- scratch (static device globals) ----------------
__device__ int      g_heads[Nsz];
__device__ int      g_tails[Nsz];
__device__ int      g_rels[Nsz];
__device__ unsigned g_trips[Nsz];        // head(11b) | rel<<11, CSR by tail
__device__ int      g_rowptr[Esz + 1];
__device__ unsigned g_mask[Esz];         // relation bitmask per tail
__device__ int      g_tidx[Esz];
__device__ int      g_ent[Bsz];
__device__ float    g_val[Bsz];
__device__ float    g_hx0[BL];
__device__ float    g_wp[Tsz * NRELc * Lsz];        // [t][r][l]
__device__ float    g_shp[Tsz * (NRELc - 1) * Lsz]; // [t][j][l]
__device__ float    g_shtp[Tsz * Ksz * Lsz];        // [t][k][l]
__device__ float    g_ab[Tsz * Lsz * 2];
__device__ float    g_tw[Lsz];
__device__ unsigned g_bm0[BMW];          // nonzero rows of s0
__device__ unsigned g_bm1[BMW];          // nonzero rows of s1
__device__ float    g_sA[Esz * BL];      // s0, [e][b*32+l]
__device__ float    g_sB[Esz * BL];      // s1
__device__ volatile unsigned g_bar;      // grid barrier counter (self-resetting)
__device__ unsigned g_fin;               // finish counter

__device__ __forceinline__ float clip01(float x) { return fminf(fmaxf(x, 0.0f), 1.0f); }

// ============ 1) streaming extraction ============
__global__ void k_setup(const float4* __restrict__ e2t,
                        const float4* __restrict__ t2e,
                        const float4* __restrict__ t2r,
                        const float*  __restrict__ input_x,
                        const float*  __restrict__ type_mat) {
    unsigned tid = blockIdx.x * blockDim.x + threadIdx.x;
    unsigned stride = gridDim.x * blockDim.x;

    for (unsigned i = tid; i < Bsz * Esz; i += stride) {
        float v = input_x[i];
        if (v != 0.0f) { g_ent[i / Esz] = (int)(i % Esz); g_val[i / Esz] = v; }
    }
    for (unsigned i = tid; i < Esz * Ksz; i += stride)
        if (type_mat[i] != 0.0f) g_tidx[i / Ksz] = (int)(i % Ksz);

    const unsigned n3 = Nsz * NRELc / 4;
    for (unsigned i = tid; i < n3; i += stride) {
        float4 v = t2r[i];
        unsigned base = i * 4u;
        if (v.x != 0.0f) { unsigned id = base + 0; g_rels[id / NRELc] = (int)(id % NRELc); }
        if (v.y != 0.0f) { unsigned id = base + 1; g_rels[id / NRELc] = (int)(id % NRELc); }
        if (v.z != 0.0f) { unsigned id = base + 2; g_rels[id / NRELc] = (int)(id % NRELc); }
        if (v.w != 0.0f) { unsigned id = base + 3; g_rels[id / NRELc] = (int)(id % NRELc); }
    }
    const unsigned n1 = (unsigned)Esz * Nsz / 4;   // e2triple [E,N] -> heads
    for (unsigned i = tid; i < n1; i += stride) {
        float4 v = e2t[i];
        unsigned base = i * 4u;
        if (v.x != 0.0f) { unsigned id = base + 0; g_heads[id % Nsz] = (int)(id / Nsz); }
        if (v.y != 0.0f) { unsigned id = base + 1; g_heads[id % Nsz] = (int)(id / Nsz); }
        if (v.z != 0.0f) { unsigned id = base + 2; g_heads[id % Nsz] = (int)(id / Nsz); }
        if (v.w != 0.0f) { unsigned id = base + 3; g_heads[id % Nsz] = (int)(id / Nsz); }
    }
    const unsigned n2 = (unsigned)Nsz * Esz / 4;   // triple2e [N,E] -> tails
    for (unsigned i = tid; i < n2; i += stride) {
        float4 v = t2e[i];
        unsigned base = i * 4u;
        if (v.x != 0.0f) { unsigned id = base + 0; g_tails[id / Esz] = (int)(id % Esz); }
        if (v.y != 0.0f) { unsigned id = base + 1; g_tails[id / Esz] = (int)(id % Esz); }
        if (v.z != 0.0f) { unsigned id = base + 2; g_tails[id / Esz] = (int)(id % Esz); }
        if (v.w != 0.0f) { unsigned id = base + 3; g_tails[id / Esz] = (int)(id % Esz); }
    }
}

// ============ 2) single block: join, bitmaps, scan, fill, tables, hx0 ============
__global__ void __launch_bounds__(1024, 1)
k_mid(const float* __restrict__ alpha, const float* __restrict__ beta,
      const float* __restrict__ alpha_x, const float* __restrict__ beta_x,
      const float* __restrict__ h_x, const float* __restrict__ h_x_type,
      const float* __restrict__ type_mat, const float* __restrict__ w,
      const float* __restrict__ h, const float* __restrict__ h_type,
      const float* __restrict__ weight) {
    __shared__ int      scnt[Esz];
    __shared__ unsigned smask[Esz];
    __shared__ int      sfill[Esz];
    __shared__ int      sscan[1024];
    __shared__ float    shx[Bsz * NRELc];
    __shared__ float    shxb[Bsz * (NRELc - 1)];
    __shared__ int      sent[Bsz];
    __shared__ float    sval[Bsz];
    __shared__ unsigned sbm0[BMW], sbm1[BMW];

    int t = threadIdx.x;
    for (int i = t; i < Esz; i += 1024) { scnt[i] = 0; smask[i] = 0u; }
    if (t < Bsz * NRELc) shx[t] = 0.0f;
    if (t < Bsz) { sent[t] = g_ent[t]; sval[t] = g_val[t]; }
    if (t < BMW) { sbm0[t] = 0u; sbm1[t] = 0u; }
    __syncthreads();

    for (int n = t; n < Nsz; n += 1024) {
        int tl = g_tails[n], r = g_rels[n], hd = g_heads[n];
        atomicAdd(&scnt[tl], 1);
        if (r < NRELc - 1) atomicOr(&smask[tl], 1u << r);
        bool hit = false;
#pragma unroll
        for (int b = 0; b < Bsz; b++)
            if (hd == sent[b]) { atomicAdd(&shx[b * NRELc + r], sval[b]); hit = true; }
        if (hit) atomicOr(&sbm0[tl >> 5], 1u << (tl & 31));
    }
    __syncthreads();
    for (int n = t; n < Nsz; n += 1024) {
        int tl = g_tails[n], hd = g_heads[n];
        if ((sbm0[hd >> 5] >> (hd & 31)) & 1u)
            atomicOr(&sbm1[tl >> 5], 1u << (tl & 31));
    }
    __syncthreads();

    if (t < BMW) { g_bm0[t] = sbm0[t]; g_bm1[t] = sbm1[t]; }
    for (int i = t; i < Esz; i += 1024) g_mask[i] = smask[i];

    // tables
    if (t < Tsz * Lsz) {
        int tt = t / Lsz, l = t % Lsz;
        const float* wr = w + (tt * Lsz + l) * NRELc;
        float m = -1e30f;
#pragma unroll
        for (int r = 0; r < NRELc; r++) m = fmaxf(m, wr[r]);
        float s = 0.0f, ev[NRELc];
#pragma unroll
        for (int r = 0; r < NRELc; r++) { ev[r] = expf(wr[r] - m); s += ev[r]; }
        float inv = 1.0f / s;
#pragma unroll
        for (int r = 0; r < NRELc; r++)
            g_wp[(tt * NRELc + r) * Lsz + l] = ev[r] * inv;
        g_ab[(tt * Lsz + l) * 2 + 0] = clip01(alpha[tt * Lsz + l] / TAU1f);
        g_ab[(tt * Lsz + l) * 2 + 1] = clip01(beta[tt * Lsz + l] / TAU1f);
    }
    for (int i = t; i < Tsz * (NRELc - 1) * Lsz; i += 1024) {
        int tt = i / ((NRELc - 1) * Lsz);
        int rem = i % ((NRELc - 1) * Lsz);
        int j = rem / Lsz, l = rem % Lsz;
        g_shp[i] = clip01(h[(tt * Lsz + l) * (NRELc - 1) + j] / TAU1f);
    }
    for (int i = t; i < Tsz * Ksz * Lsz; i += 1024) {
        int tt = i / (Ksz * Lsz);
        int rem = i % (Ksz * Lsz);
        int k = rem / Lsz, l = rem % Lsz;
        g_shtp[i] = clip01(h_type[(tt * Lsz + l) * Ksz + k] / TAU1f);
    }
    if (t < Lsz) g_tw[t] = tanhf(weight[t]);

    // exclusive scan of tail counts -> rowptr
    int c0 = (2 * t < Esz) ? scnt[2 * t] : 0;
    int c1 = (2 * t + 1 < Esz) ? scnt[2 * t + 1] : 0;
    sscan[t] = c0 + c1;
    __syncthreads();
    for (int off = 1; off < 1024; off <<= 1) {
        int v = (t >= off) ? sscan[t - off] : 0;
        __syncthreads();
        sscan[t] += v;
        __syncthreads();
    }
    int excl = (t > 0) ? sscan[t - 1] : 0;
    if (2 * t < Esz)     { g_rowptr[2 * t] = excl;          sfill[2 * t] = excl; }
    if (2 * t + 1 < Esz) { g_rowptr[2 * t + 1] = excl + c0; sfill[2 * t + 1] = excl + c0; }
    if (t == 0) g_rowptr[Esz] = Nsz;

    if (t < Bsz * (NRELc - 1)) {
        int b = t / (NRELc - 1), j = t % (NRELc - 1);
        int col = (j < 12) ? (12 + j) : (j - 12);
        shxb[t] = clip01(shx[b * NRELc + col]);
    }
    __syncthreads();

    if (t < BL) {
        int b = t / Lsz, l = t % Lsz;
        float a  = clip01(alpha[l] / TAU1f);
        float bb = clip01(beta[l] / TAU1f);
        float gate = 1.0f - clip01(clip01(alpha_x[l] / TAU1f) + clip01(beta_x[l] / TAU1f));
        float htx = 0.0f;
#pragma unroll
        for (int k = 0; k < Ksz; k++)
            htx += type_mat[sent[b] * Ksz + k] * clip01(h_x_type[l * Ksz + k] / TAU1f);
        htx *= sval[b];
        float hxl = 0.0f;
#pragma unroll
        for (int j = 0; j < NRELc - 1; j++)
            hxl += shxb[b * (NRELc - 1) + j] * clip01(h_x[l * (NRELc - 1) + j] / TAU1f);
        g_hx0[t] = clip01(a * htx + bb * hxl) + gate;
    }
    __syncthreads();

    for (int n = t; n < Nsz; n += 1024) {
        int tl = g_tails[n];
        int pos = atomicAdd(&sfill[tl], 1);
        g_trips[pos] = (unsigned)g_heads[n] | ((unsigned)g_rels[n] << 11);
    }
}

// ============ helpers for the fused prop ============
__device__ __forceinline__ void grid_barrier(unsigned goal) {
    __syncthreads();
    if (threadIdx.x == 0) {
        __threadfence();
        atomicAdd((unsigned*)&g_bar, 1u);
        while (g_bar < goal) { __nanosleep(64); }
        __threadfence();
    }
    __syncthreads();
}

template <int T>
__device__ __forceinline__ void compute_shid(int tid, int e0, float shid[TPB][Lsz]) {
    if (tid < TPB * Lsz) {
        int gg = tid >> 5, l = tid & 31;
        int ee = e0 + gg;
        float a  = g_ab[(T * Lsz + l) * 2 + 0];
        float bb = g_ab[(T * Lsz + l) * 2 + 1];
        float s1 = g_shtp[(T * Ksz + g_tidx[ee]) * Lsz + l];
        float s2 = 0.0f;
        unsigned m = g_mask[ee];
        while (m) { int jj = __ffs(m) - 1; s2 += g_shp[(T * (NRELc - 1) + jj) * Lsz + l]; m &= m - 1; }
        shid[gg][l] = clip01(a * s1 + bb * s2) + (1.0f - clip01(a + bb));
    }
}

// ============ 3) fused 3-phase propagation, one launch ============
__global__ void __launch_bounds__(TPB * COL4, 8)
k_prop_fused(float* __restrict__ out) {
    const int tid = threadIdx.x;
    const int g = tid >> 6;
    const int c = tid & 63;
    const int b = c >> 3;
    const int e0 = blockIdx.x * TPB;
    const int e  = e0 + g;

    __shared__ float shid[TPB][Lsz];
    __shared__ unsigned sbm0[BMW], sbm1[BMW];

    if (tid < BMW) sbm0[tid] = g_bm0[tid];
    else if (tid < 2 * BMW) sbm1[tid - BMW] = g_bm1[tid - BMW];

    const float4* wp4 = (const float4*)g_wp;
    const int beg = g_rowptr[e];
    const int end = g_rowptr[e + 1];

    __syncthreads();
    const bool act0 = (sbm0[e >> 5] >> (e & 31)) & 1u;
    const bool act1 = (sbm1[e >> 5] >> (e & 31)) & 1u;

    // ================= phase 0: input -> s0 (rows in bm0 only) =================
    compute_shid<0>(tid, e0, shid);
    __syncthreads();
    if (act0) {
        int sentb = g_ent[b]; float svalb = g_val[b];
        float4 acc = make_float4(0.f, 0.f, 0.f, 0.f);
        for (int j = beg; j < end; j++) {
            unsigned u = __ldg(&g_trips[j]);
            if ((int)(u & 0x7ffu) == sentb) {
                float4 wv = wp4[(0 * NRELc + (u >> 11)) * 8 + (c & 7)];
                acc.x = fmaf(svalb, wv.x, acc.x);
                acc.y = fmaf(svalb, wv.y, acc.y);
                acc.z = fmaf(svalb, wv.z, acc.z);
                acc.w = fmaf(svalb, wv.w, acc.w);
            }
        }
        float4 hid = ((const float4*)shid[g])[c & 7];
        float4 sc = ((const float4*)g_hx0)[c];
        ((float4*)g_sA)[e * COL4 + c] = make_float4(
            acc.x * hid.x * sc.x, acc.y * hid.y * sc.y,
            acc.z * hid.z * sc.z, acc.w * hid.w * sc.w);
    }
    grid_barrier(PGRID);

    // ================= phase 1: s0 -> s1 (rows in bm1 only, bm0-filtered loads) =================
    compute_shid<1>(tid, e0, shid);
    __syncthreads();
    if (act1) {
        float4 acc = make_float4(0.f, 0.f, 0.f, 0.f);
        int j = beg;
        unsigned u_next = (j < end) ? __ldg(&g_trips[j]) : 0u;
        while (j < end) {
            unsigned u = u_next;
            if (j + 1 < end) u_next = __ldg(&g_trips[j + 1]);
            unsigned head = u & 0x7ffu;
            if ((sbm0[head >> 5] >> (head & 31)) & 1u) {
                float4 v = ((const float4*)g_sA)[head * COL4 + c];
                float4 wv = wp4[(1 * NRELc + (u >> 11)) * 8 + (c & 7)];
                acc.x = fmaf(v.x, wv.x, acc.x);
                acc.y = fmaf(v.y, wv.y, acc.y);
                acc.z = fmaf(v.z, wv.z, acc.z);
                acc.w = fmaf(v.w, wv.w, acc.w);
            }
            ++j;
        }
        float4 hid = ((const float4*)shid[g])[c & 7];
        ((float4*)g_sB)[e * COL4 + c] = make_float4(
            acc.x * hid.x, acc.y * hid.y, acc.z * hid.z, acc.w * hid.w);
    }
    grid_barrier(2 * PGRID);

    // ================= phase 2: s1 -> out (dense, bm1-filtered loads) =================
    compute_shid<2>(tid, e0, shid);
    __syncthreads();
    {
        float4 acc = make_float4(0.f, 0.f, 0.f, 0.f);
        int j = beg;
        unsigned u_next = (j < end) ? __ldg(&g_trips[j]) : 0u;
        while (j < end) {
            unsigned u = u_next;
            if (j + 1 < end) u_next = __ldg(&g_trips[j + 1]);
            unsigned head = u & 0x7ffu;
            if ((sbm1[head >> 5] >> (head & 31)) & 1u) {
                float4 v = ((const float4*)g_sB)[head * COL4 + c];
                float4 wv = wp4[(2 * NRELc + (u >> 11)) * 8 + (c & 7)];
                acc.x = fmaf(v.x, wv.x, acc.x);
                acc.y = fmaf(v.y, wv.y, acc.y);
                acc.z = fmaf(v.z, wv.z, acc.z);
                acc.w = fmaf(v.w, wv.w, acc.w);
            }
            ++j;
        }
        float4 hid = ((const float4*)shid[g])[c & 7];
        float4 tw = ((const float4*)g_tw)[c & 7];
        float r = acc.x * hid.x * tw.x + acc.y * hid.y * tw.y
                + acc.z * hid.z * tw.z + acc.w * hid.w * tw.w;
#pragma unroll
        for (int off = 4; off > 0; off >>= 1)
            r += __shfl_xor_sync(0xffffffffu, r, off);
        if ((c & 7) == 0) out[b * Esz + e] = r;
    }

    // ---- reset barrier counters for next graph replay (last block to finish) ----
    __syncthreads();
    if (tid == 0) {
        unsigned prev = atomicAdd(&g_fin, 1u);
        if (prev == (unsigned)gridDim.x - 1) { g_bar = 0u; g_fin = 0u; }
    }
}

// ---------------- launch ----------------
extern "C" void kernel_launch(void* const* d_in, const int* in_sizes, int n_in,
                              void* d_out, int out_size) {
    const float* input_x  = (const float*)d_in[0];
    const float* type_mat = (const float*)d_in[1];
    const float* e2triple = (const float*)d_in[2];
    const float* triple2e = (const float*)d_in[3];
    const float* triple2r = (const float*)d_in[4];
    const float* w        = (const float*)d_in[5];
    const float* weight   = (const float*)d_in[6];
    const float* h        = (const float*)d_in[7];
    const float* h_x      = (const float*)d_in[8];
    const float* h_type   = (const float*)d_in[9];
    const float* h_x_type = (const float*)d_in[10];
    const float* alpha    = (const float*)d_in[11];
    const float* beta     = (const float*)d_in[12];
    const float* alpha_x  = (const float*)d_in[13];
    const float* beta_x   = (const float*)d_in[14];
    float* out = (float*)d_out;

    k_setup<<<1184, 256>>>((const float4*)e2triple, (const float4*)triple2e,
                           (const float4*)triple2r, input_x, type_mat);
    k_mid<<<1, 1024>>>(alpha, beta, alpha_x, beta_x, h_x, h_x_type,
                       type_mat, w, h, h_type, weight);
    k_prop_fused<<<PGRID, TPB * COL4>>>(out);
}

// round 13
// speedup vs baseline: 1.2753x; 1.2065x over previous
#include <cuda_runtime.h>
#include <math.h>

#define Bsz 8
#define Esz 2000
#define Nsz 10000
#define NRELc 25
#define Ksz 16
#define Tsz 3
#define Lsz 32
#define TAU1f 10.0f
#define BL 256
#define COL4 64
#define TPB 2
#define BMW 64
#define PGRID (Esz / TPB)    // 1000 blocks
#define TRIPS_PER_BLOCK (Nsz / PGRID)   // 10

// ---------------- scratch ----------------
__device__ int      g_heads[Nsz];
__device__ unsigned g_tails[Nsz];        // tail(11b) | slot<<11  (slot = index within tail)
__device__ int      g_rels[Nsz];
__device__ unsigned g_trips[Nsz];        // head(11b) | rel<<11, CSR by tail
__device__ int      g_cnt[Esz];          // tail degree (zeroed at end of fused kernel)
__device__ int      g_rowptr[Esz + 1];
__device__ unsigned g_mask[Esz];         // relation bitmask per tail (idempotent atomicOr)
__device__ int      g_tidx[Esz];
__device__ int      g_ent[Bsz];
__device__ float    g_val[Bsz];
__device__ float    g_hx_acc[Bsz * NRELc];   // zeroed at end of fused kernel
__device__ float    g_hx0[BL];
__device__ float    g_wp[Tsz * NRELc * Lsz];
__device__ float    g_shp[Tsz * (NRELc - 1) * Lsz];
__device__ float    g_shtp[Tsz * Ksz * Lsz];
__device__ float    g_ab[Tsz * Lsz * 2];
__device__ float    g_tw[Lsz];
__device__ unsigned g_bm0[BMW];          // idempotent
__device__ unsigned g_bm1[BMW];
__device__ float    g_sA[Esz * BL];
__device__ float    g_sB[Esz * BL];
__device__ volatile unsigned g_bar;
__device__ unsigned g_fin;

__device__ __forceinline__ float clip01(float x) { return fminf(fmaxf(x, 0.0f), 1.0f); }

// ============ 1) streaming extraction (uint4 fast path) + counts/slots ============
__global__ void k_setup(const uint4* __restrict__ e2t,
                        const uint4* __restrict__ t2e,
                        const uint4* __restrict__ t2r,
                        const float* __restrict__ input_x,
                        const float* __restrict__ type_mat) {
    unsigned tid = blockIdx.x * blockDim.x + threadIdx.x;
    unsigned stride = gridDim.x * blockDim.x;

    for (unsigned i = tid; i < Bsz * Esz; i += stride) {
        float v = input_x[i];
        if (v != 0.0f) { g_ent[i / Esz] = (int)(i % Esz); g_val[i / Esz] = v; }
    }
    for (unsigned i = tid; i < Esz * Ksz; i += stride)
        if (type_mat[i] != 0.0f) g_tidx[i / Ksz] = (int)(i % Ksz);

    const unsigned n3 = Nsz * NRELc / 4;
    for (unsigned i = tid; i < n3; i += stride) {
        uint4 v = t2r[i];
        if (v.x | v.y | v.z | v.w) {
            unsigned base = i * 4u;
            if (v.x) { unsigned id = base + 0; g_rels[id / NRELc] = (int)(id % NRELc); }
            if (v.y) { unsigned id = base + 1; g_rels[id / NRELc] = (int)(id % NRELc); }
            if (v.z) { unsigned id = base + 2; g_rels[id / NRELc] = (int)(id % NRELc); }
            if (v.w) { unsigned id = base + 3; g_rels[id / NRELc] = (int)(id % NRELc); }
        }
    }
    const unsigned n1 = (unsigned)Esz * Nsz / 4;   // e2triple [E,N] -> heads
    for (unsigned i = tid; i < n1; i += stride) {
        uint4 v = e2t[i];
        if (v.x | v.y | v.z | v.w) {
            unsigned base = i * 4u;
            if (v.x) { unsigned id = base + 0; g_heads[id % Nsz] = (int)(id / Nsz); }
            if (v.y) { unsigned id = base + 1; g_heads[id % Nsz] = (int)(id / Nsz); }
            if (v.z) { unsigned id = base + 2; g_heads[id % Nsz] = (int)(id / Nsz); }
            if (v.w) { unsigned id = base + 3; g_heads[id % Nsz] = (int)(id / Nsz); }
        }
    }
    const unsigned n2 = (unsigned)Nsz * Esz / 4;   // triple2e [N,E] -> tails + slot
    for (unsigned i = tid; i < n2; i += stride) {
        uint4 v = t2e[i];
        if (v.x | v.y | v.z | v.w) {
            unsigned base = i * 4u;
#pragma unroll
            for (int k = 0; k < 4; k++) {
                unsigned wv = (k == 0) ? v.x : (k == 1) ? v.y : (k == 2) ? v.z : v.w;
                if (wv) {
                    unsigned id = base + k;
                    unsigned n = id / Esz, tl = id % Esz;
                    unsigned slot = (unsigned)atomicAdd(&g_cnt[tl], 1);
                    g_tails[n] = tl | (slot << 11);
                }
            }
        }
    }
}

// ============ helpers ============
__device__ __forceinline__ void grid_barrier(unsigned goal) {
    __syncthreads();
    if (threadIdx.x == 0) {
        __threadfence();
        atomicAdd((unsigned*)&g_bar, 1u);
        while (g_bar < goal) { __nanosleep(64); }
        __threadfence();
    }
    __syncthreads();
}

template <int T>
__device__ __forceinline__ void compute_shid(int tid, int e0, float shid[TPB][Lsz]) {
    if (tid < TPB * Lsz) {
        int gg = tid >> 5, l = tid & 31;
        int ee = e0 + gg;
        float a  = g_ab[(T * Lsz + l) * 2 + 0];
        float bb = g_ab[(T * Lsz + l) * 2 + 1];
        float s1 = g_shtp[(T * Ksz + g_tidx[ee]) * Lsz + l];
        float s2 = 0.0f;
        unsigned m = g_mask[ee];
        while (m) { int jj = __ffs(m) - 1; s2 += g_shp[(T * (NRELc - 1) + jj) * Lsz + l]; m &= m - 1; }
        shid[gg][l] = clip01(a * s1 + bb * s2) + (1.0f - clip01(a + bb));
    }
}

// ============ 2) fused: join + scan + tables + fill + hx0 + 3 prop phases ============
__global__ void __launch_bounds__(TPB * COL4, 8)
k_fused(const float* __restrict__ alpha, const float* __restrict__ beta,
        const float* __restrict__ alpha_x, const float* __restrict__ beta_x,
        const float* __restrict__ h_x, const float* __restrict__ h_x_type,
        const float* __restrict__ w, const float* __restrict__ h,
        const float* __restrict__ h_type, const float* __restrict__ weight,
        float* __restrict__ out) {
    const int tid = threadIdx.x;
    const int bi = blockIdx.x;
    const int g = tid >> 6;
    const int c = tid & 63;
    const int b = c >> 3;
    const int e0 = bi * TPB;
    const int e  = e0 + g;
    const int n0 = bi * TRIPS_PER_BLOCK;

    __shared__ float shid[TPB][Lsz];
    __shared__ unsigned sbm0[BMW], sbm1[BMW];
    __shared__ int ws[4];

    // ================= stage A =================
    // join (threads 0..9 handle this block's 10 triples)
    if (tid < TRIPS_PER_BLOCK) {
        int n = n0 + tid;
        unsigned tw_ = g_tails[n];
        int tl = (int)(tw_ & 0x7ffu);
        int r = g_rels[n], hd = g_heads[n];
        if (r < NRELc - 1) atomicOr(&g_mask[tl], 1u << r);
#pragma unroll
        for (int bb2 = 0; bb2 < Bsz; bb2++) {
            if (hd == g_ent[bb2]) {
                atomicAdd(&g_hx_acc[bb2 * NRELc + r], g_val[bb2]);
                atomicOr(&g_bm0[tl >> 5], 1u << (tl & 31));
            }
        }
    }
    // block 0: exclusive scan of g_cnt -> g_rowptr
    if (bi == 0) {
        int loc[16]; int s = 0;
        int base = tid * 16;
#pragma unroll
        for (int k = 0; k < 16; k++) {
            int idx = base + k;
            loc[k] = s;
            if (idx < Esz) s += g_cnt[idx];
        }
        int lane = tid & 31, wrp = tid >> 5;
        int v = s;
#pragma unroll
        for (int off = 1; off < 32; off <<= 1) {
            int o = __shfl_up_sync(0xffffffffu, v, off);
            if (lane >= off) v += o;
        }
        if (lane == 31) ws[wrp] = v;
        __syncthreads();
        int wo = 0;
        for (int k = 0; k < wrp; k++) wo += ws[k];
        int excl = v - s + wo;
#pragma unroll
        for (int k = 0; k < 16; k++) {
            int idx = base + k;
            if (idx < Esz) g_rowptr[idx] = excl + loc[k];
        }
        if (tid == 127) g_rowptr[Esz] = Nsz;
    }
    // tables
    if (bi == 999) {
        if (tid < Tsz * Lsz) {
            int tt = tid / Lsz, l = tid % Lsz;
            const float* wr = w + (tt * Lsz + l) * NRELc;
            float m = -1e30f;
#pragma unroll
            for (int r = 0; r < NRELc; r++) m = fmaxf(m, wr[r]);
            float s = 0.0f, ev[NRELc];
#pragma unroll
            for (int r = 0; r < NRELc; r++) { ev[r] = expf(wr[r] - m); s += ev[r]; }
            float inv = 1.0f / s;
#pragma unroll
            for (int r = 0; r < NRELc; r++)
                g_wp[(tt * NRELc + r) * Lsz + l] = ev[r] * inv;
            g_ab[(tt * Lsz + l) * 2 + 0] = clip01(alpha[tt * Lsz + l] / TAU1f);
            g_ab[(tt * Lsz + l) * 2 + 1] = clip01(beta[tt * Lsz + l] / TAU1f);
        } else if (tid < Tsz * Lsz + Lsz) {
            int l = tid - Tsz * Lsz;
            g_tw[l] = tanhf(weight[l]);
        }
    }
    if (bi >= 980 && bi < 998) {
        int i = (bi - 980) * 128 + tid;   // 0..2303
        int tt = i / ((NRELc - 1) * Lsz);
        int rem = i % ((NRELc - 1) * Lsz);
        int j = rem / Lsz, l = rem % Lsz;
        g_shp[i] = clip01(h[(tt * Lsz + l) * (NRELc - 1) + j] / TAU1f);
    }
    if (bi >= 960 && bi < 972) {
        int i = (bi - 960) * 128 + tid;   // 0..1535
        int tt = i / (Ksz * Lsz);
        int rem = i % (Ksz * Lsz);
        int k = rem / Lsz, l = rem % Lsz;
        g_shtp[i] = clip01(h_type[(tt * Lsz + l) * Ksz + k] / TAU1f);
    }
    grid_barrier(PGRID);

    // ================= stage B =================
    // bm1 + atomic-free CSR fill for this block's triples
    if (tid < TRIPS_PER_BLOCK) {
        int n = n0 + tid;
        unsigned tw_ = g_tails[n];
        int tl = (int)(tw_ & 0x7ffu);
        unsigned slot = tw_ >> 11;
        int hd = g_heads[n], r = g_rels[n];
        if ((g_bm0[hd >> 5] >> (hd & 31)) & 1u)
            atomicOr(&g_bm1[tl >> 5], 1u << (tl & 31));
        g_trips[g_rowptr[tl] + slot] = (unsigned)hd | ((unsigned)r << 11);
    }
    // hx0 by block 998
    if (bi == 998) {
        for (int t2 = tid; t2 < BL; t2 += 128) {
            int bb2 = t2 / Lsz, l = t2 & 31;
            int entb = g_ent[bb2]; float valb = g_val[bb2];
            float a  = clip01(alpha[l] / TAU1f);
            float bb = clip01(beta[l] / TAU1f);
            float gate = 1.0f - clip01(clip01(alpha_x[l] / TAU1f) + clip01(beta_x[l] / TAU1f));
            float htx = clip01(h_x_type[l * Ksz + g_tidx[entb]] / TAU1f) * valb;
            float hxl = 0.0f;
#pragma unroll
            for (int j = 0; j < NRELc - 1; j++) {
                int col = (j < 12) ? (12 + j) : (j - 12);
                hxl += clip01(g_hx_acc[bb2 * NRELc + col]) * clip01(h_x[l * (NRELc - 1) + j] / TAU1f);
            }
            g_hx0[t2] = clip01(a * htx + bb * hxl) + gate;
        }
    }
    grid_barrier(2 * PGRID);

    // load bitmaps + row range
    if (tid < BMW) sbm0[tid] = g_bm0[tid];
    else if (tid < 2 * BMW) sbm1[tid - BMW] = g_bm1[tid - BMW];
    __syncthreads();
    const int beg = g_rowptr[e];
    const int end = g_rowptr[e + 1];
    const bool act0 = (sbm0[e >> 5] >> (e & 31)) & 1u;
    const bool act1 = (sbm1[e >> 5] >> (e & 31)) & 1u;
    const float4* wp4 = (const float4*)g_wp;

    // ================= phase 0 =================
    compute_shid<0>(tid, e0, shid);
    __syncthreads();
    if (act0) {
        int sentb = g_ent[b]; float svalb = g_val[b];
        float4 acc = make_float4(0.f, 0.f, 0.f, 0.f);
        for (int j = beg; j < end; j++) {
            unsigned u = __ldg(&g_trips[j]);
            if ((int)(u & 0x7ffu) == sentb) {
                float4 wv = wp4[(0 * NRELc + (u >> 11)) * 8 + (c & 7)];
                acc.x = fmaf(svalb, wv.x, acc.x);
                acc.y = fmaf(svalb, wv.y, acc.y);
                acc.z = fmaf(svalb, wv.z, acc.z);
                acc.w = fmaf(svalb, wv.w, acc.w);
            }
        }
        float4 hid = ((const float4*)shid[g])[c & 7];
        float4 sc = ((const float4*)g_hx0)[c];
        ((float4*)g_sA)[e * COL4 + c] = make_float4(
            acc.x * hid.x * sc.x, acc.y * hid.y * sc.y,
            acc.z * hid.z * sc.z, acc.w * hid.w * sc.w);
    }
    grid_barrier(3 * PGRID);

    // ================= phase 1 =================
    compute_shid<1>(tid, e0, shid);
    __syncthreads();
    if (act1) {
        float4 acc = make_float4(0.f, 0.f, 0.f, 0.f);
        int j = beg;
        unsigned u_next = (j < end) ? __ldg(&g_trips[j]) : 0u;
        while (j < end) {
            unsigned u = u_next;
            if (j + 1 < end) u_next = __ldg(&g_trips[j + 1]);
            unsigned head = u & 0x7ffu;
            if ((sbm0[head >> 5] >> (head & 31)) & 1u) {
                float4 v = ((const float4*)g_sA)[head * COL4 + c];
                float4 wv = wp4[(1 * NRELc + (u >> 11)) * 8 + (c & 7)];
                acc.x = fmaf(v.x, wv.x, acc.x);
                acc.y = fmaf(v.y, wv.y, acc.y);
                acc.z = fmaf(v.z, wv.z, acc.z);
                acc.w = fmaf(v.w, wv.w, acc.w);
            }
            ++j;
        }
        float4 hid = ((const float4*)shid[g])[c & 7];
        ((float4*)g_sB)[e * COL4 + c] = make_float4(
            acc.x * hid.x, acc.y * hid.y, acc.z * hid.z, acc.w * hid.w);
    }
    grid_barrier(4 * PGRID);

    // ================= phase 2 =================
    compute_shid<2>(tid, e0, shid);
    __syncthreads();
    {
        float4 acc = make_float4(0.f, 0.f, 0.f, 0.f);
        int j = beg;
        unsigned u_next = (j < end) ? __ldg(&g_trips[j]) : 0u;
        while (j < end) {
            unsigned u = u_next;
            if (j + 1 < end) u_next = __ldg(&g_trips[j + 1]);
            unsigned head = u & 0x7ffu;
            if ((sbm1[head >> 5] >> (head & 31)) & 1u) {
                float4 v = ((const float4*)g_sB)[head * COL4 + c];
                float4 wv = wp4[(2 * NRELc + (u >> 11)) * 8 + (c & 7)];
                acc.x = fmaf(v.x, wv.x, acc.x);
                acc.y = fmaf(v.y, wv.y, acc.y);
                acc.z = fmaf(v.z, wv.z, acc.z);
                acc.w = fmaf(v.w, wv.w, acc.w);
            }
            ++j;
        }
        float4 hid = ((const float4*)shid[g])[c & 7];
        float4 tw = ((const float4*)g_tw)[c & 7];
        float r = acc.x * hid.x * tw.x + acc.y * hid.y * tw.y
                + acc.z * hid.z * tw.z + acc.w * hid.w * tw.w;
#pragma unroll
        for (int off = 4; off > 0; off >>= 1)
            r += __shfl_xor_sync(0xffffffffu, r, off);
        if ((c & 7) == 0) out[b * Esz + e] = r;
    }

    // ---- cleanup for next graph replay ----
    if (tid < TPB) g_cnt[e0 + tid] = 0;
    if (bi == 0 && tid < 128) {
        for (int i = tid; i < Bsz * NRELc; i += 128) g_hx_acc[i] = 0.0f;
    }
    __syncthreads();
    if (tid == 0) {
        unsigned prev = atomicAdd(&g_fin, 1u);
        if (prev == (unsigned)gridDim.x - 1) { g_bar = 0u; g_fin = 0u; }
    }
}

// ---------------- launch ----------------
extern "C" void kernel_launch(void* const* d_in, const int* in_sizes, int n_in,
                              void* d_out, int out_size) {
    const float* input_x  = (const float*)d_in[0];
    const float* type_mat = (const float*)d_in[1];
    const float* e2triple = (const float*)d_in[2];
    const float* triple2e = (const float*)d_in[3];
    const float* triple2r = (const float*)d_in[4];
    const float* w        = (const float*)d_in[5];
    const float* weight   = (const float*)d_in[6];
    const float* h        = (const float*)d_in[7];
    const float* h_x      = (const float*)d_in[8];
    const float* h_type   = (const float*)d_in[9];
    const float* h_x_type = (const float*)d_in[10];
    const float* alpha    = (const float*)d_in[11];
    const float* beta     = (const float*)d_in[12];
    const float* alpha_x  = (const float*)d_in[13];
    const float* beta_x   = (const float*)d_in[14];
    float* out = (float*)d_out;

    k_setup<<<1184, 256>>>((const uint4*)e2triple, (const uint4*)triple2e,
                           (const uint4*)triple2r, input_x, type_mat);
    k_fused<<<PGRID, TPB * COL4>>>(alpha, beta, alpha_x, beta_x, h_x, h_x_type,
                                   w, h, h_type, weight, out);
}

// round 14
// speedup vs baseline: 1.5642x; 1.2266x over previous
#include <cuda_runtime.h>
#include <math.h>

#define Bsz 8
#define Esz 2000
#define Nsz 10000
#define NRELc 25
#define Ksz 16
#define Tsz 3
#define Lsz 32
#define TAU1f 10.0f
#define BL 256
#define COL4 64
#define TPB 4
#define SLOTS 32
#define BMW 64
#define PGRID (Esz / TPB)    // 500 blocks

// ---------------- scratch ----------------
__device__ int      g_heads[Nsz];
__device__ int      g_rels[Nsz];
__device__ int      g_slotn[Esz * SLOTS];  // n-index per (tail, slot)
__device__ int      g_cnt[Esz];            // tail degree (zeroed in cleanup)
__device__ int      g_tidx[Esz];
__device__ int      g_ent[Bsz];
__device__ float    g_val[Bsz];
__device__ float    g_hx_acc[Bsz * NRELc]; // zeroed in cleanup
__device__ float    g_wp[Tsz * NRELc * Lsz];
__device__ float    g_shp[Tsz * (NRELc - 1) * Lsz];
__device__ float    g_shtp[Tsz * Ksz * Lsz];
__device__ float    g_ab[Tsz * Lsz * 2];
__device__ float    g_tw[Lsz];
__device__ unsigned g_bm0[BMW];            // zeroed in cleanup
__device__ unsigned g_bm1[BMW];            // zeroed in cleanup
__device__ float    g_sA[Esz * BL];
__device__ float    g_sB[Esz * BL];
__device__ volatile unsigned g_bar;
__device__ unsigned g_fin;

__device__ __forceinline__ float clip01(float x) { return fminf(fmaxf(x, 0.0f), 1.0f); }

// ============ 1) streaming extraction (4x batched loads) ============
__global__ void k_setup(const uint4* __restrict__ e2t,
                        const uint4* __restrict__ t2e,
                        const uint4* __restrict__ t2r,
                        const float* __restrict__ input_x,
                        const float* __restrict__ type_mat) {
    const unsigned tid = blockIdx.x * blockDim.x + threadIdx.x;
    const unsigned stride = gridDim.x * blockDim.x;

    for (unsigned i = tid; i < Bsz * Esz; i += stride) {
        float v = input_x[i];
        if (v != 0.0f) { g_ent[i / Esz] = (int)(i % Esz); g_val[i / Esz] = v; }
    }
    for (unsigned i = tid; i < Esz * Ksz; i += stride)
        if (type_mat[i] != 0.0f) g_tidx[i / Ksz] = (int)(i % Ksz);

    const unsigned n3 = Nsz * NRELc / 4;
    for (unsigned i = tid; i < n3; i += stride) {
        uint4 v = t2r[i];
        if (v.x | v.y | v.z | v.w) {
            unsigned base = i * 4u;
            if (v.x) { unsigned id = base + 0; g_rels[id / NRELc] = (int)(id % NRELc); }
            if (v.y) { unsigned id = base + 1; g_rels[id / NRELc] = (int)(id % NRELc); }
            if (v.z) { unsigned id = base + 2; g_rels[id / NRELc] = (int)(id % NRELc); }
            if (v.w) { unsigned id = base + 3; g_rels[id / NRELc] = (int)(id % NRELc); }
        }
    }

    // e2triple [E,N] -> heads
    const unsigned n1 = (unsigned)Esz * Nsz / 4;
    {
        unsigned i = tid;
        for (; i + 3 * stride < n1; i += 4 * stride) {
            uint4 a0 = e2t[i], a1 = e2t[i + stride], a2 = e2t[i + 2 * stride], a3 = e2t[i + 3 * stride];
#define PROC_H(vv, ii) \
            if ((vv).x | (vv).y | (vv).z | (vv).w) { \
                unsigned base = (ii) * 4u; \
                if ((vv).x) { unsigned id = base + 0; g_heads[id % Nsz] = (int)(id / Nsz); } \
                if ((vv).y) { unsigned id = base + 1; g_heads[id % Nsz] = (int)(id / Nsz); } \
                if ((vv).z) { unsigned id = base + 2; g_heads[id % Nsz] = (int)(id / Nsz); } \
                if ((vv).w) { unsigned id = base + 3; g_heads[id % Nsz] = (int)(id / Nsz); } }
            PROC_H(a0, i) PROC_H(a1, i + stride) PROC_H(a2, i + 2 * stride) PROC_H(a3, i + 3 * stride)
        }
        for (; i < n1; i += stride) { uint4 a = e2t[i]; PROC_H(a, i) }
    }
    // triple2e [N,E] -> slot scatter
    const unsigned n2 = (unsigned)Nsz * Esz / 4;
    {
        unsigned i = tid;
        for (; i + 3 * stride < n2; i += 4 * stride) {
            uint4 a0 = t2e[i], a1 = t2e[i + stride], a2 = t2e[i + 2 * stride], a3 = t2e[i + 3 * stride];
#define PROC_T(vv, ii) \
            if ((vv).x | (vv).y | (vv).z | (vv).w) { \
                unsigned base = (ii) * 4u; \
                unsigned ws[4] = {(vv).x, (vv).y, (vv).z, (vv).w}; \
                _Pragma("unroll") \
                for (int k = 0; k < 4; k++) if (ws[k]) { \
                    unsigned id = base + k; \
                    unsigned n = id / Esz, tl = id % Esz; \
                    int slot = atomicAdd(&g_cnt[tl], 1); \
                    if (slot < SLOTS) g_slotn[tl * SLOTS + slot] = (int)n; } }
            PROC_T(a0, i) PROC_T(a1, i + stride) PROC_T(a2, i + 2 * stride) PROC_T(a3, i + 3 * stride)
        }
        for (; i < n2; i += stride) { uint4 a = t2e[i]; PROC_T(a, i) }
    }
}

// ============ helpers ============
__device__ __forceinline__ void grid_barrier(unsigned goal) {
    __syncthreads();
    if (threadIdx.x == 0) {
        __threadfence();
        atomicAdd((unsigned*)&g_bar, 1u);
        while (g_bar < goal) { __nanosleep(64); }
        __threadfence();
    }
    __syncthreads();
}

// ============ 2) fused everything ============
__global__ void __launch_bounds__(256, 4)
k_fused(const float* __restrict__ alpha, const float* __restrict__ beta,
        const float* __restrict__ alpha_x, const float* __restrict__ beta_x,
        const float* __restrict__ h_x, const float* __restrict__ h_x_type,
        const float* __restrict__ w, const float* __restrict__ h,
        const float* __restrict__ h_type, const float* __restrict__ weight,
        float* __restrict__ out) {
    const int tid = threadIdx.x;
    const int bi = blockIdx.x;
    const int g = tid >> 6;         // row group 0..3
    const int c = tid & 63;         // float4 column slot
    const int b = c >> 3;
    const int e0 = bi * TPB;
    const int e  = e0 + g;

    __shared__ unsigned strip[TPB][SLOTS];
    __shared__ float    shid[TPB][Lsz];
    __shared__ float    shx0[BL];
    __shared__ unsigned smaskl[TPB];
    __shared__ int      sflags[TPB];   // bit0 act0, bit1 act1
    __shared__ int      scnt[TPB];
    __shared__ int      sent[Bsz];
    __shared__ float    sval[Bsz];
    __shared__ unsigned sbm0[BMW], sbm1[BMW];
    __shared__ int      sany0;

    if (tid < TPB) { smaskl[tid] = 0u; sflags[tid] = 0; scnt[tid] = min(g_cnt[e0 + tid], SLOTS); }
    if (tid >= 32 && tid < 32 + Bsz) { sent[tid - 32] = g_ent[tid - 32]; sval[tid - 32] = g_val[tid - 32]; }
    __syncthreads();

    // ===== stage A: local trips + mask + hx join + bm0 publish; tables by high blocks =====
    if (tid < TPB * SLOTS) {
        int row = tid >> 5, slot = tid & 31;
        if (slot < scnt[row]) {
            int n = g_slotn[(e0 + row) * SLOTS + slot];
            int hd = g_heads[n], r = g_rels[n];
            strip[row][slot] = (unsigned)hd | ((unsigned)r << 11);
            if (r < NRELc - 1) atomicOr(&smaskl[row], 1u << r);
#pragma unroll
            for (int b2 = 0; b2 < Bsz; b2++) {
                if (hd == sent[b2]) {
                    atomicAdd(&g_hx_acc[b2 * NRELc + r], sval[b2]);
                    atomicOr(&sflags[row], 1);
                }
            }
        }
    }
    // tables
    if (bi == PGRID - 1) {
        if (tid < Tsz * Lsz) {
            int tt = tid / Lsz, l = tid % Lsz;
            const float* wr = w + (tt * Lsz + l) * NRELc;
            float m = -1e30f;
#pragma unroll
            for (int r = 0; r < NRELc; r++) m = fmaxf(m, wr[r]);
            float s = 0.0f, ev[NRELc];
#pragma unroll
            for (int r = 0; r < NRELc; r++) { ev[r] = expf(wr[r] - m); s += ev[r]; }
            float inv = 1.0f / s;
#pragma unroll
            for (int r = 0; r < NRELc; r++)
                g_wp[(tt * NRELc + r) * Lsz + l] = ev[r] * inv;
            g_ab[(tt * Lsz + l) * 2 + 0] = clip01(alpha[tt * Lsz + l] / TAU1f);
            g_ab[(tt * Lsz + l) * 2 + 1] = clip01(beta[tt * Lsz + l] / TAU1f);
        } else if (tid < Tsz * Lsz + Lsz) {
            int l = tid - Tsz * Lsz;
            g_tw[l] = tanhf(weight[l]);
        }
    }
    if (bi >= 480 && bi < 489) {
        int i = (bi - 480) * 256 + tid;
        if (i < Tsz * (NRELc - 1) * Lsz) {
            int tt = i / ((NRELc - 1) * Lsz);
            int rem = i % ((NRELc - 1) * Lsz);
            int j = rem / Lsz, l = rem % Lsz;
            g_shp[i] = clip01(h[(tt * Lsz + l) * (NRELc - 1) + j] / TAU1f);
        }
    }
    if (bi >= 470 && bi < 476) {
        int i = (bi - 470) * 256 + tid;
        int tt = i / (Ksz * Lsz);
        int rem = i % (Ksz * Lsz);
        int k = rem / Lsz, l = rem % Lsz;
        g_shtp[i] = clip01(h_type[(tt * Lsz + l) * Ksz + k] / TAU1f);
    }
    __syncthreads();
    if (tid < TPB && (sflags[tid] & 1)) {
        int ee = e0 + tid;
        atomicOr(&g_bm0[ee >> 5], 1u << (ee & 31));
    }
    grid_barrier(PGRID);

    // ===== stage B: bm1 + hx0 + shid0 + phase 0 =====
    if (tid < BMW) sbm0[tid] = g_bm0[tid];
    if (tid == 0) sany0 = (sflags[0] | sflags[1] | sflags[2] | sflags[3]) & 1;
    __syncthreads();

    if (tid < TPB * SLOTS) {
        int row = tid >> 5, slot = tid & 31;
        if (slot < scnt[row]) {
            unsigned hd = strip[row][slot] & 0x7ffu;
            if ((sbm0[hd >> 5] >> (hd & 31)) & 1u) atomicOr(&sflags[row], 2);
        }
    }
    // hx0 (gated; needs complete g_hx_acc)
    if (sany0) {
        int b2 = tid >> 5, l = tid & 31;
        int entb = sent[b2]; float valb = sval[b2];
        float a  = clip01(alpha[l] / TAU1f);
        float bb = clip01(beta[l] / TAU1f);
        float gate = 1.0f - clip01(clip01(alpha_x[l] / TAU1f) + clip01(beta_x[l] / TAU1f));
        float htx = clip01(h_x_type[l * Ksz + g_tidx[entb]] / TAU1f) * valb;
        float hxl = 0.0f;
#pragma unroll
        for (int j = 0; j < NRELc - 1; j++) {
            int col = (j < 12) ? (12 + j) : (j - 12);
            hxl += clip01(g_hx_acc[b2 * NRELc + col]) * clip01(h_x[l * (NRELc - 1) + j] / TAU1f);
        }
        shx0[tid] = clip01(a * htx + bb * hxl) + gate;
    }
    // shid<0>
    if (tid < TPB * Lsz) {
        int row = tid >> 5, l = tid & 31;
        int ee = e0 + row;
        float a  = g_ab[(0 * Lsz + l) * 2 + 0];
        float bb = g_ab[(0 * Lsz + l) * 2 + 1];
        float s1 = g_shtp[(0 * Ksz + g_tidx[ee]) * Lsz + l];
        float s2 = 0.0f;
        unsigned m = smaskl[row];
        while (m) { int jj = __ffs(m) - 1; s2 += g_shp[(0 * (NRELc - 1) + jj) * Lsz + l]; m &= m - 1; }
        shid[row][l] = clip01(a * s1 + bb * s2) + (1.0f - clip01(a + bb));
    }
    __syncthreads();
    if (tid < TPB && (sflags[tid] & 2)) {
        int ee = e0 + tid;
        atomicOr(&g_bm1[ee >> 5], 1u << (ee & 31));
    }
    const float4* wp4 = (const float4*)g_wp;
    if (sflags[g] & 1) {
        int sentb = sent[b]; float svalb = sval[b];
        float4 acc = make_float4(0.f, 0.f, 0.f, 0.f);
        int cnt = scnt[g];
        for (int j = 0; j < cnt; j++) {
            unsigned u = strip[g][j];
            if ((int)(u & 0x7ffu) == sentb) {
                float4 wv = wp4[(0 * NRELc + (u >> 11)) * 8 + (c & 7)];
                acc.x = fmaf(svalb, wv.x, acc.x);
                acc.y = fmaf(svalb, wv.y, acc.y);
                acc.z = fmaf(svalb, wv.z, acc.z);
                acc.w = fmaf(svalb, wv.w, acc.w);
            }
        }
        float4 hid = ((const float4*)shid[g])[c & 7];
        float4 sc = ((const float4*)shx0)[c];
        ((float4*)g_sA)[e * COL4 + c] = make_float4(
            acc.x * hid.x * sc.x, acc.y * hid.y * sc.y,
            acc.z * hid.z * sc.z, acc.w * hid.w * sc.w);
    }
    grid_barrier(2 * PGRID);

    // ===== phase 1: s0 -> s1 =====
    if (tid < BMW) sbm1[tid] = g_bm1[tid];
    if (tid < TPB * Lsz) {
        int row = tid >> 5, l = tid & 31;
        int ee = e0 + row;
        float a  = g_ab[(1 * Lsz + l) * 2 + 0];
        float bb = g_ab[(1 * Lsz + l) * 2 + 1];
        float s1 = g_shtp[(1 * Ksz + g_tidx[ee]) * Lsz + l];
        float s2 = 0.0f;
        unsigned m = smaskl[row];
        while (m) { int jj = __ffs(m) - 1; s2 += g_shp[(1 * (NRELc - 1) + jj) * Lsz + l]; m &= m - 1; }
        shid[row][l] = clip01(a * s1 + bb * s2) + (1.0f - clip01(a + bb));
    }
    __syncthreads();
    if (sflags[g] & 2) {
        float4 acc = make_float4(0.f, 0.f, 0.f, 0.f);
        int cnt = scnt[g];
        for (int j = 0; j < cnt; j++) {
            unsigned u = strip[g][j];
            unsigned head = u & 0x7ffu;
            if ((sbm0[head >> 5] >> (head & 31)) & 1u) {
                float4 v = ((const float4*)g_sA)[head * COL4 + c];
                float4 wv = wp4[(1 * NRELc + (u >> 11)) * 8 + (c & 7)];
                acc.x = fmaf(v.x, wv.x, acc.x);
                acc.y = fmaf(v.y, wv.y, acc.y);
                acc.z = fmaf(v.z, wv.z, acc.z);
                acc.w = fmaf(v.w, wv.w, acc.w);
            }
        }
        float4 hid = ((const float4*)shid[g])[c & 7];
        ((float4*)g_sB)[e * COL4 + c] = make_float4(
            acc.x * hid.x, acc.y * hid.y, acc.z * hid.z, acc.w * hid.w);
    }
    grid_barrier(3 * PGRID);

    // ===== phase 2: s1 -> out =====
    if (tid < TPB * Lsz) {
        int row = tid >> 5, l = tid & 31;
        int ee = e0 + row;
        float a  = g_ab[(2 * Lsz + l) * 2 + 0];
        float bb = g_ab[(2 * Lsz + l) * 2 + 1];
        float s1 = g_shtp[(2 * Ksz + g_tidx[ee]) * Lsz + l];
        float s2 = 0.0f;
        unsigned m = smaskl[row];
        while (m) { int jj = __ffs(m) - 1; s2 += g_shp[(2 * (NRELc - 1) + jj) * Lsz + l]; m &= m - 1; }
        shid[row][l] = clip01(a * s1 + bb * s2) + (1.0f - clip01(a + bb));
    }
    __syncthreads();
    {
        float4 acc = make_float4(0.f, 0.f, 0.f, 0.f);
        int cnt = scnt[g];
        for (int j = 0; j < cnt; j++) {
            unsigned u = strip[g][j];
            unsigned head = u & 0x7ffu;
            if ((sbm1[head >> 5] >> (head & 31)) & 1u) {
                float4 v = ((const float4*)g_sB)[head * COL4 + c];
                float4 wv = wp4[(2 * NRELc + (u >> 11)) * 8 + (c & 7)];
                acc.x = fmaf(v.x, wv.x, acc.x);
                acc.y = fmaf(v.y, wv.y, acc.y);
                acc.z = fmaf(v.z, wv.z, acc.z);
                acc.w = fmaf(v.w, wv.w, acc.w);
            }
        }
        float4 hid = ((const float4*)shid[g])[c & 7];
        float4 tw = ((const float4*)g_tw)[c & 7];
        float r = acc.x * hid.x * tw.x + acc.y * hid.y * tw.y
                + acc.z * hid.z * tw.z + acc.w * hid.w * tw.w;
#pragma unroll
        for (int off = 4; off > 0; off >>= 1)
            r += __shfl_xor_sync(0xffffffffu, r, off);
        if ((c & 7) == 0) out[b * Esz + e] = r;
    }

    // ===== cleanup for next graph replay =====
    if (tid < TPB) g_cnt[e0 + tid] = 0;
    if (bi == 0) {
        if (tid < BMW) { g_bm0[tid] = 0u; g_bm1[tid] = 0u; }
        if (tid >= 64 && tid < 64 + Bsz * NRELc) g_hx_acc[tid - 64] = 0.0f;
    }
    __syncthreads();
    if (tid == 0) {
        unsigned prev = atomicAdd(&g_fin, 1u);
        if (prev == (unsigned)gridDim.x - 1) { g_bar = 0u; g_fin = 0u; }
    }
}

// ---------------- launch ----------------
extern "C" void kernel_launch(void* const* d_in, const int* in_sizes, int n_in,
                              void* d_out, int out_size) {
    const float* input_x  = (const float*)d_in[0];
    const float* type_mat = (const float*)d_in[1];
    const float* e2triple = (const float*)d_in[2];
    const float* triple2e = (const float*)d_in[3];
    const float* triple2r = (const float*)d_in[4];
    const float* w        = (const float*)d_in[5];
    const float* weight   = (const float*)d_in[6];
    const float* h        = (const float*)d_in[7];
    const float* h_x      = (const float*)d_in[8];
    const float* h_type   = (const float*)d_in[9];
    const float* h_x_type = (const float*)d_in[10];
    const float* alpha    = (const float*)d_in[11];
    const float* beta     = (const float*)d_in[12];
    const float* alpha_x  = (const float*)d_in[13];
    const float* beta_x   = (const float*)d_in[14];
    float* out = (float*)d_out;

    k_setup<<<1184, 256>>>((const uint4*)e2triple, (const uint4*)triple2e,
                           (const uint4*)triple2r, input_x, type_mat);
    k_fused<<<PGRID, 256>>>(alpha, beta, alpha_x, beta_x, h_x, h_x_type,
                            w, h, h_type, weight, out);
}

// round 15
// speedup vs baseline: 1.6856x; 1.0776x over previous
#include <cuda_runtime.h>
#include <math.h>

#define Bsz 8
#define Esz 2000
#define Nsz 10000
#define NRELc 25
#define Ksz 16
#define Tsz 3
#define Lsz 32
#define TAU1f 10.0f
#define BL 256
#define COL4 64
#define TPB 8
#define SLOTS 32
#define BMW 64
#define PGRID (Esz / TPB)    // 250 blocks

// ---------------- scratch ----------------
__device__ int      g_heads[Nsz];
__device__ int      g_rels[Nsz];
__device__ int      g_slotn[Esz * SLOTS];  // n-index per (tail, slot)
__device__ int      g_cnt[Esz];            // tail degree (zeroed in cleanup)
__device__ int      g_tidx[Esz];
__device__ int      g_ent[Bsz];
__device__ float    g_val[Bsz];
__device__ float    g_hx_acc[Bsz * NRELc]; // zeroed in cleanup
__device__ float    g_wp[Tsz * NRELc * Lsz];
__device__ float    g_shp[Tsz * (NRELc - 1) * Lsz];
__device__ float    g_shtp[Tsz * Ksz * Lsz];
__device__ float    g_ab[Tsz * Lsz * 2];
__device__ float    g_tw[Lsz];
__device__ unsigned g_bm0[BMW];            // zeroed in cleanup
__device__ unsigned g_bm1[BMW];            // zeroed in cleanup
__device__ float    g_sA[Esz * BL];
__device__ float    g_sB[Esz * BL];
__device__ volatile unsigned g_bar;
__device__ unsigned g_fin;

__device__ __forceinline__ float clip01(float x) { return fminf(fmaxf(x, 0.0f), 1.0f); }

// ============ 1) streaming extraction (4x batched, evict-first) ============
__global__ void k_setup(const uint4* __restrict__ e2t,
                        const uint4* __restrict__ t2e,
                        const uint4* __restrict__ t2r,
                        const float* __restrict__ input_x,
                        const float* __restrict__ type_mat) {
    const unsigned tid = blockIdx.x * blockDim.x + threadIdx.x;
    const unsigned stride = gridDim.x * blockDim.x;

    for (unsigned i = tid; i < Bsz * Esz; i += stride) {
        float v = input_x[i];
        if (v != 0.0f) { g_ent[i / Esz] = (int)(i % Esz); g_val[i / Esz] = v; }
    }
    for (unsigned i = tid; i < Esz * Ksz; i += stride)
        if (type_mat[i] != 0.0f) g_tidx[i / Ksz] = (int)(i % Ksz);

    const unsigned n3 = Nsz * NRELc / 4;
    for (unsigned i = tid; i < n3; i += stride) {
        uint4 v = __ldcs(&t2r[i]);
        if (v.x | v.y | v.z | v.w) {
            unsigned base = i * 4u;
            if (v.x) { unsigned id = base + 0; g_rels[id / NRELc] = (int)(id % NRELc); }
            if (v.y) { unsigned id = base + 1; g_rels[id / NRELc] = (int)(id % NRELc); }
            if (v.z) { unsigned id = base + 2; g_rels[id / NRELc] = (int)(id % NRELc); }
            if (v.w) { unsigned id = base + 3; g_rels[id / NRELc] = (int)(id % NRELc); }
        }
    }

    const unsigned n1 = (unsigned)Esz * Nsz / 4;   // e2triple -> heads
    {
        unsigned i = tid;
        for (; i + 3 * stride < n1; i += 4 * stride) {
            uint4 a0 = __ldcs(&e2t[i]);
            uint4 a1 = __ldcs(&e2t[i + stride]);
            uint4 a2 = __ldcs(&e2t[i + 2 * stride]);
            uint4 a3 = __ldcs(&e2t[i + 3 * stride]);
#define PROC_H(vv, ii) \
            if ((vv).x | (vv).y | (vv).z | (vv).w) { \
                unsigned base = (ii) * 4u; \
                if ((vv).x) { unsigned id = base + 0; g_heads[id % Nsz] = (int)(id / Nsz); } \
                if ((vv).y) { unsigned id = base + 1; g_heads[id % Nsz] = (int)(id / Nsz); } \
                if ((vv).z) { unsigned id = base + 2; g_heads[id % Nsz] = (int)(id / Nsz); } \
                if ((vv).w) { unsigned id = base + 3; g_heads[id % Nsz] = (int)(id / Nsz); } }
            PROC_H(a0, i) PROC_H(a1, i + stride) PROC_H(a2, i + 2 * stride) PROC_H(a3, i + 3 * stride)
        }
        for (; i < n1; i += stride) { uint4 a = __ldcs(&e2t[i]); PROC_H(a, i) }
    }
    const unsigned n2 = (unsigned)Nsz * Esz / 4;   // triple2e -> slot scatter
    {
        unsigned i = tid;
        for (; i + 3 * stride < n2; i += 4 * stride) {
            uint4 a0 = __ldcs(&t2e[i]);
            uint4 a1 = __ldcs(&t2e[i + stride]);
            uint4 a2 = __ldcs(&t2e[i + 2 * stride]);
            uint4 a3 = __ldcs(&t2e[i + 3 * stride]);
#define PROC_T(vv, ii) \
            if ((vv).x | (vv).y | (vv).z | (vv).w) { \
                unsigned base = (ii) * 4u; \
                unsigned ws[4] = {(vv).x, (vv).y, (vv).z, (vv).w}; \
                _Pragma("unroll") \
                for (int k = 0; k < 4; k++) if (ws[k]) { \
                    unsigned id = base + k; \
                    unsigned n = id / Esz, tl = id % Esz; \
                    int slot = atomicAdd(&g_cnt[tl], 1); \
                    if (slot < SLOTS) g_slotn[tl * SLOTS + slot] = (int)n; } }
            PROC_T(a0, i) PROC_T(a1, i + stride) PROC_T(a2, i + 2 * stride) PROC_T(a3, i + 3 * stride)
        }
        for (; i < n2; i += stride) { uint4 a = __ldcs(&t2e[i]); PROC_T(a, i) }
    }
}

// ============ helpers ============
__device__ __forceinline__ void grid_barrier(unsigned goal) {
    __syncthreads();
    if (threadIdx.x == 0) {
        __threadfence();
        atomicAdd((unsigned*)&g_bar, 1u);
        while (g_bar < goal) { __nanosleep(64); }
        __threadfence();
    }
    __syncthreads();
}

// ============ 2) fused: stage A/B + 3 prop phases; TPB=8, no spills ============
__global__ void __launch_bounds__(256, 2)
k_fused(const float* __restrict__ alpha, const float* __restrict__ beta,
        const float* __restrict__ alpha_x, const float* __restrict__ beta_x,
        const float* __restrict__ h_x, const float* __restrict__ h_x_type,
        const float* __restrict__ w, const float* __restrict__ h,
        const float* __restrict__ h_type, const float* __restrict__ weight,
        float* __restrict__ out) {
    const int tid = threadIdx.x;
    const int bi = blockIdx.x;
    const int g = tid >> 5;          // row group 0..7
    const int c2 = tid & 31;         // 32 threads per row; thread owns float4 slots {2c2, 2c2+1}
    const int ca = 2 * c2, cb = 2 * c2 + 1;
    const int b = c2 >> 2;           // batch for these 8 columns
    const int e0 = bi * TPB;
    const int e  = e0 + g;

    __shared__ unsigned strip[TPB][SLOTS];
    __shared__ float    shid[TPB][Lsz];
    __shared__ float    shx0[BL];
    __shared__ unsigned smaskl[TPB];
    __shared__ int      sflags[TPB];
    __shared__ int      scnt[TPB];
    __shared__ int      sent[Bsz];
    __shared__ float    sval[Bsz];
    __shared__ unsigned sbm0[BMW], sbm1[BMW];
    __shared__ int      sany0;

    if (tid < TPB) { smaskl[tid] = 0u; sflags[tid] = 0; scnt[tid] = min(g_cnt[e0 + tid], SLOTS); }
    if (tid >= 32 && tid < 32 + Bsz) { sent[tid - 32] = g_ent[tid - 32]; sval[tid - 32] = g_val[tid - 32]; }
    __syncthreads();

    // ===== stage A: local strips + mask + hx join; tables by high blocks =====
    {
        int row = g, slot = c2;
        if (slot < scnt[row]) {
            int n = g_slotn[(e0 + row) * SLOTS + slot];
            int hd = g_heads[n], r = g_rels[n];
            strip[row][slot] = (unsigned)hd | ((unsigned)r << 11);
            if (r < NRELc - 1) atomicOr(&smaskl[row], 1u << r);
#pragma unroll
            for (int b2 = 0; b2 < Bsz; b2++) {
                if (hd == sent[b2]) {
                    atomicAdd(&g_hx_acc[b2 * NRELc + r], sval[b2]);
                    atomicOr(&sflags[row], 1);
                }
            }
        }
    }
    // tables (blocks near end of grid)
    if (bi == PGRID - 1) {
        if (tid < Tsz * Lsz) {
            int tt = tid / Lsz, l = tid % Lsz;
            const float* wr = w + (tt * Lsz + l) * NRELc;
            float m = -1e30f;
#pragma unroll
            for (int r = 0; r < NRELc; r++) m = fmaxf(m, wr[r]);
            float s = 0.0f, ev[NRELc];
#pragma unroll
            for (int r = 0; r < NRELc; r++) { ev[r] = expf(wr[r] - m); s += ev[r]; }
            float inv = 1.0f / s;
#pragma unroll
            for (int r = 0; r < NRELc; r++)
                g_wp[(tt * NRELc + r) * Lsz + l] = ev[r] * inv;
            g_ab[(tt * Lsz + l) * 2 + 0] = clip01(alpha[tt * Lsz + l] / TAU1f);
            g_ab[(tt * Lsz + l) * 2 + 1] = clip01(beta[tt * Lsz + l] / TAU1f);
        } else if (tid < Tsz * Lsz + Lsz) {
            int l = tid - Tsz * Lsz;
            g_tw[l] = tanhf(weight[l]);
        }
    }
    if (bi >= 230 && bi < 239) {
        int i = (bi - 230) * 256 + tid;
        if (i < Tsz * (NRELc - 1) * Lsz) {
            int tt = i / ((NRELc - 1) * Lsz);
            int rem = i % ((NRELc - 1) * Lsz);
            int j = rem / Lsz, l = rem % Lsz;
            g_shp[i] = clip01(h[(tt * Lsz + l) * (NRELc - 1) + j] / TAU1f);
        }
    }
    if (bi >= 220 && bi < 226) {
        int i = (bi - 220) * 256 + tid;
        int tt = i / (Ksz * Lsz);
        int rem = i % (Ksz * Lsz);
        int k = rem / Lsz, l = rem % Lsz;
        g_shtp[i] = clip01(h_type[(tt * Lsz + l) * Ksz + k] / TAU1f);
    }
    __syncthreads();
    if (tid < TPB && (sflags[tid] & 1)) {
        int ee = e0 + tid;
        atomicOr(&g_bm0[ee >> 5], 1u << (ee & 31));
    }
    grid_barrier(PGRID);

    // ===== stage B: bm1 flags + hx0 + shid0 + phase 0 =====
    if (tid < BMW) sbm0[tid] = g_bm0[tid];
    if (tid == 0) {
        int o = 0;
#pragma unroll
        for (int r2 = 0; r2 < TPB; r2++) o |= sflags[r2];
        sany0 = o & 1;
    }
    __syncthreads();

    {
        int row = g, slot = c2;
        if (slot < scnt[row]) {
            unsigned hd = strip[row][slot] & 0x7ffu;
            if ((sbm0[hd >> 5] >> (hd & 31)) & 1u) atomicOr(&sflags[row], 2);
        }
    }
    if (sany0) {
        int b2 = tid >> 5, l = tid & 31;
        int entb = sent[b2]; float valb = sval[b2];
        float a  = clip01(alpha[l] / TAU1f);
        float bb = clip01(beta[l] / TAU1f);
        float gate = 1.0f - clip01(clip01(alpha_x[l] / TAU1f) + clip01(beta_x[l] / TAU1f));
        float htx = clip01(h_x_type[l * Ksz + g_tidx[entb]] / TAU1f) * valb;
        float hxl = 0.0f;
#pragma unroll
        for (int j = 0; j < NRELc - 1; j++) {
            int col = (j < 12) ? (12 + j) : (j - 12);
            hxl += clip01(g_hx_acc[b2 * NRELc + col]) * clip01(h_x[l * (NRELc - 1) + j] / TAU1f);
        }
        shx0[tid] = clip01(a * htx + bb * hxl) + gate;
    }
    {
        int row = g, l = c2;
        int ee = e0 + row;
        float a  = g_ab[(0 * Lsz + l) * 2 + 0];
        float bb = g_ab[(0 * Lsz + l) * 2 + 1];
        float s1 = g_shtp[(0 * Ksz + g_tidx[ee]) * Lsz + l];
        float s2 = 0.0f;
        unsigned m = smaskl[row];
        while (m) { int jj = __ffs(m) - 1; s2 += g_shp[(0 * (NRELc - 1) + jj) * Lsz + l]; m &= m - 1; }
        shid[row][l] = clip01(a * s1 + bb * s2) + (1.0f - clip01(a + bb));
    }
    __syncthreads();
    if (tid < TPB && (sflags[tid] & 2)) {
        int ee = e0 + tid;
        atomicOr(&g_bm1[ee >> 5], 1u << (ee & 31));
    }
    const float4* wp4 = (const float4*)g_wp;
    if (sflags[g] & 1) {
        int sentb = sent[b]; float svalb = sval[b];
        float4 acca = make_float4(0.f, 0.f, 0.f, 0.f);
        float4 accb = make_float4(0.f, 0.f, 0.f, 0.f);
        int cnt = scnt[g];
        for (int j = 0; j < cnt; j++) {
            unsigned u = strip[g][j];
            if ((int)(u & 0x7ffu) == sentb) {
                unsigned rbase = (0 * NRELc + (u >> 11)) * 8;
                float4 wa = wp4[rbase + (ca & 7)];
                float4 wb = wp4[rbase + (cb & 7)];
                acca.x = fmaf(svalb, wa.x, acca.x); acca.y = fmaf(svalb, wa.y, acca.y);
                acca.z = fmaf(svalb, wa.z, acca.z); acca.w = fmaf(svalb, wa.w, acca.w);
                accb.x = fmaf(svalb, wb.x, accb.x); accb.y = fmaf(svalb, wb.y, accb.y);
                accb.z = fmaf(svalb, wb.z, accb.z); accb.w = fmaf(svalb, wb.w, accb.w);
            }
        }
        float4 ha = ((const float4*)shid[g])[ca & 7];
        float4 hb = ((const float4*)shid[g])[cb & 7];
        float4 xa = ((const float4*)shx0)[ca];
        float4 xb = ((const float4*)shx0)[cb];
        ((float4*)g_sA)[e * COL4 + ca] = make_float4(
            acca.x * ha.x * xa.x, acca.y * ha.y * xa.y, acca.z * ha.z * xa.z, acca.w * ha.w * xa.w);
        ((float4*)g_sA)[e * COL4 + cb] = make_float4(
            accb.x * hb.x * xb.x, accb.y * hb.y * xb.y, accb.z * hb.z * xb.z, accb.w * hb.w * xb.w);
    }
    grid_barrier(2 * PGRID);

    // ===== phase 1: s0 -> s1 =====
    if (tid < BMW) sbm1[tid] = g_bm1[tid];
    {
        int row = g, l = c2;
        int ee = e0 + row;
        float a  = g_ab[(1 * Lsz + l) * 2 + 0];
        float bb = g_ab[(1 * Lsz + l) * 2 + 1];
        float s1 = g_shtp[(1 * Ksz + g_tidx[ee]) * Lsz + l];
        float s2 = 0.0f;
        unsigned m = smaskl[row];
        while (m) { int jj = __ffs(m) - 1; s2 += g_shp[(1 * (NRELc - 1) + jj) * Lsz + l]; m &= m - 1; }
        shid[row][l] = clip01(a * s1 + bb * s2) + (1.0f - clip01(a + bb));
    }
    __syncthreads();
    if (sflags[g] & 2) {
        float4 acca = make_float4(0.f, 0.f, 0.f, 0.f);
        float4 accb = make_float4(0.f, 0.f, 0.f, 0.f);
        int cnt = scnt[g];
        for (int j = 0; j < cnt; j++) {
            unsigned u = strip[g][j];
            unsigned head = u & 0x7ffu;
            if ((sbm0[head >> 5] >> (head & 31)) & 1u) {
                float4 va = ((const float4*)g_sA)[head * COL4 + ca];
                float4 vb = ((const float4*)g_sA)[head * COL4 + cb];
                unsigned rbase = (1 * NRELc + (u >> 11)) * 8;
                float4 wa = wp4[rbase + (ca & 7)];
                float4 wb = wp4[rbase + (cb & 7)];
                acca.x = fmaf(va.x, wa.x, acca.x); acca.y = fmaf(va.y, wa.y, acca.y);
                acca.z = fmaf(va.z, wa.z, acca.z); acca.w = fmaf(va.w, wa.w, acca.w);
                accb.x = fmaf(vb.x, wb.x, accb.x); accb.y = fmaf(vb.y, wb.y, accb.y);
                accb.z = fmaf(vb.z, wb.z, accb.z); accb.w = fmaf(vb.w, wb.w, accb.w);
            }
        }
        float4 ha = ((const float4*)shid[g])[ca & 7];
        float4 hb = ((const float4*)shid[g])[cb & 7];
        ((float4*)g_sB)[e * COL4 + ca] = make_float4(
            acca.x * ha.x, acca.y * ha.y, acca.z * ha.z, acca.w * ha.w);
        ((float4*)g_sB)[e * COL4 + cb] = make_float4(
            accb.x * hb.x, accb.y * hb.y, accb.z * hb.z, accb.w * hb.w);
    }
    grid_barrier(3 * PGRID);

    // ===== phase 2: s1 -> out =====
    {
        int row = g, l = c2;
        int ee = e0 + row;
        float a  = g_ab[(2 * Lsz + l) * 2 + 0];
        float bb = g_ab[(2 * Lsz + l) * 2 + 1];
        float s1 = g_shtp[(2 * Ksz + g_tidx[ee]) * Lsz + l];
        float s2 = 0.0f;
        unsigned m = smaskl[row];
        while (m) { int jj = __ffs(m) - 1; s2 += g_shp[(2 * (NRELc - 1) + jj) * Lsz + l]; m &= m - 1; }
        shid[row][l] = clip01(a * s1 + bb * s2) + (1.0f - clip01(a + bb));
    }
    __syncthreads();
    {
        float4 acca = make_float4(0.f, 0.f, 0.f, 0.f);
        float4 accb = make_float4(0.f, 0.f, 0.f, 0.f);
        int cnt = scnt[g];
        for (int j = 0; j < cnt; j++) {
            unsigned u = strip[g][j];
            unsigned head = u & 0x7ffu;
            if ((sbm1[head >> 5] >> (head & 31)) & 1u) {
                float4 va = ((const float4*)g_sB)[head * COL4 + ca];
                float4 vb = ((const float4*)g_sB)[head * COL4 + cb];
                unsigned rbase = (2 * NRELc + (u >> 11)) * 8;
                float4 wa = wp4[rbase + (ca & 7)];
                float4 wb = wp4[rbase + (cb & 7)];
                acca.x = fmaf(va.x, wa.x, acca.x); acca.y = fmaf(va.y, wa.y, acca.y);
                acca.z = fmaf(va.z, wa.z, acca.z); acca.w = fmaf(va.w, wa.w, acca.w);
                accb.x = fmaf(vb.x, wb.x, accb.x); accb.y = fmaf(vb.y, wb.y, accb.y);
                accb.z = fmaf(vb.z, wb.z, accb.z); accb.w = fmaf(vb.w, wb.w, accb.w);
            }
        }
        float4 ha = ((const float4*)shid[g])[ca & 7];
        float4 hb = ((const float4*)shid[g])[cb & 7];
        float4 ta = ((const float4*)g_tw)[ca & 7];
        float4 tb = ((const float4*)g_tw)[cb & 7];
        float r = acca.x * ha.x * ta.x + acca.y * ha.y * ta.y
                + acca.z * ha.z * ta.z + acca.w * ha.w * ta.w
                + accb.x * hb.x * tb.x + accb.y * hb.y * tb.y
                + accb.z * hb.z * tb.z + accb.w * hb.w * tb.w;
        r += __shfl_xor_sync(0xffffffffu, r, 1);
        r += __shfl_xor_sync(0xffffffffu, r, 2);
        if ((c2 & 3) == 0) out[b * Esz + e] = r;
    }

    // ===== cleanup for next graph replay =====
    if (tid < TPB) g_cnt[e0 + tid] = 0;
    if (bi == 0) {
        if (tid < BMW) { g_bm0[tid] = 0u; g_bm1[tid] = 0u; }
        if (tid >= 64 && tid < 64 + Bsz * NRELc) g_hx_acc[tid - 64] = 0.0f;
    }
    __syncthreads();
    if (tid == 0) {
        unsigned prev = atomicAdd(&g_fin, 1u);
        if (prev == (unsigned)gridDim.x - 1) { g_bar = 0u; g_fin = 0u; }
    }
}

// ---------------- launch ----------------
extern "C" void kernel_launch(void* const* d_in, const int* in_sizes, int n_in,
                              void* d_out, int out_size) {
    const float* input_x  = (const float*)d_in[0];
    const float* type_mat = (const float*)d_in[1];
    const float* e2triple = (const float*)d_in[2];
    const float* triple2e = (const float*)d_in[3];
    const float* triple2r = (const float*)d_in[4];
    const float* w        = (const float*)d_in[5];
    const float* weight   = (const float*)d_in[6];
    const float* h        = (const float*)d_in[7];
    const float* h_x      = (const float*)d_in[8];
    const float* h_type   = (const float*)d_in[9];
    const float* h_x_type = (const float*)d_in[10];
    const float* alpha    = (const float*)d_in[11];
    const float* beta     = (const float*)d_in[12];
    const float* alpha_x  = (const float*)d_in[13];
    const float* beta_x   = (const float*)d_in[14];
    float* out = (float*)d_out;

    k_setup<<<1184, 256>>>((const uint4*)e2triple, (const uint4*)triple2e,
                           (const uint4*)triple2r, input_x, type_mat);
    k_fused<<<PGRID, 256>>>(alpha, beta, alpha_x, beta_x, h_x, h_x_type,
                            w, h, h_type, weight, out);
}